// round 1
// baseline (speedup 1.0000x reference)
#include <cuda_runtime.h>
#include <math.h>

#define S_LEN 4096
#define DM    1024
#define NH    16
#define HD    64
#define WIN   64

// Intermediate buffers (no allocations allowed): q,k,v,attn_out each [S, DM] fp32
__device__ float g_q [S_LEN * DM];
__device__ float g_k [S_LEN * DM];
__device__ float g_v [S_LEN * DM];
__device__ float g_ao[S_LEN * DM];

// ---------------------------------------------------------------------------
// SGEMM (NT): C[M,N] = A[M,K] @ B[N,K]^T       (A, B row-major, K contiguous)
// 128x128 tile, BK=16, 256 threads, 8x8 microtile, double-buffered smem.
// blockIdx.z selects one of 3 (B, C) pairs so QKV projections are one launch.
// ---------------------------------------------------------------------------
#define BM 128
#define BN 128
#define BK 16

__global__ __launch_bounds__(256, 2) void sgemm_nt(
    const float* __restrict__ A,
    const float* __restrict__ Ba, const float* __restrict__ Bb, const float* __restrict__ Bc,
    float* __restrict__ Ca, float* __restrict__ Cb, float* __restrict__ Cc,
    int M, int N, int K)
{
    const float* __restrict__ B = (blockIdx.z == 0) ? Ba : (blockIdx.z == 1 ? Bb : Bc);
    float* __restrict__ C       = (blockIdx.z == 0) ? Ca : (blockIdx.z == 1 ? Cb : Cc);

    __shared__ float As[2][BK][BM];
    __shared__ float Bs[2][BK][BN];

    const int tid = threadIdx.x;
    const int m0 = blockIdx.y * BM;
    const int n0 = blockIdx.x * BN;

    // loader mapping: 256 threads load 128x16 tile as float4 (2 rows each)
    const int lr = tid >> 2;          // 0..63
    const int lc = (tid & 3) << 2;    // 0,4,8,12

    const float* Aptr = A + (size_t)(m0 + lr) * K + lc;
    const float* Bptr = B + (size_t)(n0 + lr) * K + lc;

    // ---- load tile 0 ----
    {
        float4 a0 = *(const float4*)(Aptr);
        float4 a1 = *(const float4*)(Aptr + (size_t)64 * K);
        float4 b0 = *(const float4*)(Bptr);
        float4 b1 = *(const float4*)(Bptr + (size_t)64 * K);
        As[0][lc+0][lr]    = a0.x; As[0][lc+1][lr]    = a0.y; As[0][lc+2][lr]    = a0.z; As[0][lc+3][lr]    = a0.w;
        As[0][lc+0][lr+64] = a1.x; As[0][lc+1][lr+64] = a1.y; As[0][lc+2][lr+64] = a1.z; As[0][lc+3][lr+64] = a1.w;
        Bs[0][lc+0][lr]    = b0.x; Bs[0][lc+1][lr]    = b0.y; Bs[0][lc+2][lr]    = b0.z; Bs[0][lc+3][lr]    = b0.w;
        Bs[0][lc+0][lr+64] = b1.x; Bs[0][lc+1][lr+64] = b1.y; Bs[0][lc+2][lr+64] = b1.z; Bs[0][lc+3][lr+64] = b1.w;
    }
    __syncthreads();

    const int tx = tid & 15;   // 0..15 -> C cols tx*4 and 64+tx*4
    const int ty = tid >> 4;   // 0..15 -> C rows ty*4 and 64+ty*4

    float acc[8][8];
    #pragma unroll
    for (int i = 0; i < 8; i++)
        #pragma unroll
        for (int j = 0; j < 8; j++) acc[i][j] = 0.0f;

    const int nTiles = K / BK;
    for (int t = 0; t < nTiles; t++) {
        const int buf = t & 1;

        // prefetch next tile (global -> regs)
        float4 na0, na1, nb0, nb1;
        if (t + 1 < nTiles) {
            const float* Ap = Aptr + (size_t)(t + 1) * BK;
            const float* Bp = Bptr + (size_t)(t + 1) * BK;
            na0 = *(const float4*)(Ap);
            na1 = *(const float4*)(Ap + (size_t)64 * K);
            nb0 = *(const float4*)(Bp);
            nb1 = *(const float4*)(Bp + (size_t)64 * K);
        }

        #pragma unroll
        for (int kk = 0; kk < BK; kk++) {
            float ar[8], br[8];
            *(float4*)&ar[0] = *(const float4*)&As[buf][kk][ty * 4];
            *(float4*)&ar[4] = *(const float4*)&As[buf][kk][ty * 4 + 64];
            *(float4*)&br[0] = *(const float4*)&Bs[buf][kk][tx * 4];
            *(float4*)&br[4] = *(const float4*)&Bs[buf][kk][tx * 4 + 64];
            #pragma unroll
            for (int i = 0; i < 8; i++)
                #pragma unroll
                for (int j = 0; j < 8; j++)
                    acc[i][j] = fmaf(ar[i], br[j], acc[i][j]);
        }

        if (t + 1 < nTiles) {
            const int nb = (t + 1) & 1;
            As[nb][lc+0][lr]    = na0.x; As[nb][lc+1][lr]    = na0.y; As[nb][lc+2][lr]    = na0.z; As[nb][lc+3][lr]    = na0.w;
            As[nb][lc+0][lr+64] = na1.x; As[nb][lc+1][lr+64] = na1.y; As[nb][lc+2][lr+64] = na1.z; As[nb][lc+3][lr+64] = na1.w;
            Bs[nb][lc+0][lr]    = nb0.x; Bs[nb][lc+1][lr]    = nb0.y; Bs[nb][lc+2][lr]    = nb0.z; Bs[nb][lc+3][lr]    = nb0.w;
            Bs[nb][lc+0][lr+64] = nb1.x; Bs[nb][lc+1][lr+64] = nb1.y; Bs[nb][lc+2][lr+64] = nb1.z; Bs[nb][lc+3][lr+64] = nb1.w;
            __syncthreads();
        }
    }

    // epilogue
    #pragma unroll
    for (int i = 0; i < 8; i++) {
        const int m = m0 + ((i < 4) ? (ty * 4 + i) : (64 + ty * 4 + i - 4));
        float* crow = C + (size_t)m * N + n0;
        float4 v0 = make_float4(acc[i][0], acc[i][1], acc[i][2], acc[i][3]);
        float4 v1 = make_float4(acc[i][4], acc[i][5], acc[i][6], acc[i][7]);
        *(float4*)&crow[tx * 4]      = v0;
        *(float4*)&crow[64 + tx * 4] = v1;
    }
}

// ---------------------------------------------------------------------------
// Sliding-window attention.
// Block = (64 queries) x (1 head), 128 threads: thread (qi, hv) with hv in {0,1}.
// QK: hv splits the 64-wide window; AV: hv splits the 64-wide head dim.
// smem: K tile [128][68], V tile [128][68], scores [64][68] (pad 68 => stride
// = 4 mod 32 => conflict-free float4 LDS across lanes).
// ---------------------------------------------------------------------------
#define ATT_PAD 68
#define ATT_SMEM_FLOATS (2 * 128 * ATT_PAD + 64 * ATT_PAD)
#define ATT_SMEM_BYTES  (ATT_SMEM_FLOATS * 4)

__global__ void swattn(const float* __restrict__ q, const float* __restrict__ k,
                       const float* __restrict__ v, float* __restrict__ o)
{
    extern __shared__ float sm[];
    float* Ks = sm;
    float* Vs = sm + 128 * ATT_PAD;
    float* Ss = sm + 2 * 128 * ATT_PAD;

    const int qstart  = blockIdx.x * 64;
    const int h       = blockIdx.y;
    const int korigin = qstart - (WIN - 1);   // local key row r -> global key korigin + r
    const int hcol    = h * HD;

    const int tid = threadIdx.x;
    const int qi  = tid & 63;
    const int hv  = tid >> 6;   // 0 or 1

    // ---- load K,V tiles (128 rows x 64 cols), zero-filled out of range ----
    for (int i = tid; i < 128 * 16; i += 128) {
        const int r  = i >> 4;
        const int c4 = (i & 15) << 2;
        const int g  = korigin + r;
        float4 kk = make_float4(0.f, 0.f, 0.f, 0.f);
        float4 vv = kk;
        if (g >= 0 && g < S_LEN) {
            kk = *(const float4*)&k[(size_t)g * DM + hcol + c4];
            vv = *(const float4*)&v[(size_t)g * DM + hcol + c4];
        }
        *(float4*)&Ks[r * ATT_PAD + c4] = kk;
        *(float4*)&Vs[r * ATT_PAD + c4] = vv;
    }

    // ---- load this query's q row into regs, pre-scaled by 1/sqrt(hd) ----
    float qreg[64];
    {
        const float* qrow = &q[(size_t)(qstart + qi) * DM + hcol];
        #pragma unroll
        for (int j = 0; j < 16; j++) {
            float4 t4 = *(const float4*)&qrow[4 * j];
            qreg[4*j+0] = t4.x * 0.125f;
            qreg[4*j+1] = t4.y * 0.125f;
            qreg[4*j+2] = t4.z * 0.125f;
            qreg[4*j+3] = t4.w * 0.125f;
        }
    }
    __syncthreads();

    // ---- scores: thread (qi,hv) computes window half [hv*32, hv*32+32) ----
    #pragma unroll 4
    for (int w = hv * 32; w < hv * 32 + 32; w++) {
        const int r = qi + w;          // local key row; global = korigin + r
        const float* kr = &Ks[r * ATT_PAD];
        float s = 0.0f;
        #pragma unroll
        for (int d = 0; d < 64; d += 4) {
            float4 kk = *(const float4*)&kr[d];
            s = fmaf(qreg[d+0], kk.x, s);
            s = fmaf(qreg[d+1], kk.y, s);
            s = fmaf(qreg[d+2], kk.z, s);
            s = fmaf(qreg[d+3], kk.w, s);
        }
        const int gkey = korigin + r;
        Ss[qi * ATT_PAD + w] = (gkey >= 0) ? s : -INFINITY;
    }
    __syncthreads();

    // ---- softmax over the 64 scores of query qi (both halves, redundant) ----
    float p[64];
    float mx = -INFINITY;
    #pragma unroll
    for (int w = 0; w < 64; w++) {
        p[w] = Ss[qi * ATT_PAD + w];
        mx = fmaxf(mx, p[w]);
    }
    float sum = 0.0f;
    #pragma unroll
    for (int w = 0; w < 64; w++) {
        p[w] = __expf(p[w] - mx);
        sum += p[w];
    }
    const float inv = 1.0f / sum;
    #pragma unroll
    for (int w = 0; w < 64; w++) p[w] *= inv;

    // ---- AV: thread (qi,hv) accumulates head dims [hv*32, hv*32+32) ----
    float accv[32];
    #pragma unroll
    for (int d = 0; d < 32; d++) accv[d] = 0.0f;

    const int dbase = hv * 32;
    for (int w = 0; w < 64; w++) {
        const float pw = p[w];
        const float* vr = &Vs[(qi + w) * ATT_PAD + dbase];
        #pragma unroll
        for (int d4 = 0; d4 < 8; d4++) {
            float4 vv = *(const float4*)&vr[4 * d4];
            accv[4*d4+0] = fmaf(pw, vv.x, accv[4*d4+0]);
            accv[4*d4+1] = fmaf(pw, vv.y, accv[4*d4+1]);
            accv[4*d4+2] = fmaf(pw, vv.z, accv[4*d4+2]);
            accv[4*d4+3] = fmaf(pw, vv.w, accv[4*d4+3]);
        }
    }

    float* orow = &o[(size_t)(qstart + qi) * DM + hcol + dbase];
    #pragma unroll
    for (int d4 = 0; d4 < 8; d4++)
        *(float4*)&orow[4 * d4] =
            make_float4(accv[4*d4+0], accv[4*d4+1], accv[4*d4+2], accv[4*d4+3]);
}

// ---------------------------------------------------------------------------
// Launch
// ---------------------------------------------------------------------------
extern "C" void kernel_launch(void* const* d_in, const int* in_sizes, int n_in,
                              void* d_out, int out_size)
{
    const float* x  = (const float*)d_in[0];
    const float* Wq = (const float*)d_in[1];
    const float* Wk = (const float*)d_in[2];
    const float* Wv = (const float*)d_in[3];
    const float* Wo = (const float*)d_in[4];
    float* out = (float*)d_out;

    float *qp, *kp, *vp, *aop;
    cudaGetSymbolAddress((void**)&qp,  g_q);
    cudaGetSymbolAddress((void**)&kp,  g_k);
    cudaGetSymbolAddress((void**)&vp,  g_v);
    cudaGetSymbolAddress((void**)&aop, g_ao);

    // QKV projections: one fused launch, grid.z picks (W, C) pair
    {
        dim3 grid(DM / BN, S_LEN / BM, 3);
        sgemm_nt<<<grid, 256>>>(x, Wq, Wk, Wv, qp, kp, vp, S_LEN, DM, DM);
    }

    // sliding-window attention
    {
        cudaFuncSetAttribute(swattn, cudaFuncAttributeMaxDynamicSharedMemorySize,
                             ATT_SMEM_BYTES);
        dim3 grid(S_LEN / 64, NH);
        swattn<<<grid, 128, ATT_SMEM_BYTES>>>(qp, kp, vp, aop);
    }

    // output projection
    {
        dim3 grid(DM / BN, S_LEN / BM, 1);
        sgemm_nt<<<grid, 256>>>(aop, Wo, Wo, Wo, out, out, out, S_LEN, DM, DM);
    }
}

// round 3
// speedup vs baseline: 2.1813x; 2.1813x over previous
#include <cuda_runtime.h>
#include <cuda_bf16.h>
#include <cstdint>
#include <math.h>

#define S_LEN 4096
#define DM    1024
#define NH    16
#define HD    64
#define WIN   64

// ---------------- device scratch (no allocations allowed) ----------------
__device__ float g_q [S_LEN * DM];
__device__ float g_k [S_LEN * DM];
__device__ float g_v [S_LEN * DM];
__device__ float g_ao[S_LEN * DM];
__device__ __nv_bfloat16 g_xh [S_LEN * DM];
__device__ __nv_bfloat16 g_xl [S_LEN * DM];
__device__ __nv_bfloat16 g_wh [4 * DM * DM];
__device__ __nv_bfloat16 g_wl [4 * DM * DM];
__device__ __nv_bfloat16 g_aoh[S_LEN * DM];
__device__ __nv_bfloat16 g_aol[S_LEN * DM];

// ---------------- PTX helpers (baseline sm_80+ features only) ----------------
__device__ __forceinline__ uint32_t smem_u32(const void* p) {
    uint32_t a;
    asm("{ .reg .u64 t; cvta.to.shared.u64 t, %1; cvt.u32.u64 %0, t; }" : "=r"(a) : "l"(p));
    return a;
}
#define CP16(dst, src) \
    asm volatile("cp.async.cg.shared.global [%0], [%1], 16;" :: "r"((uint32_t)(dst)), "l"(src) : "memory")
#define CP_COMMIT() asm volatile("cp.async.commit_group;" ::: "memory")
#define CP_WAIT1()  asm volatile("cp.async.wait_group 1;" ::: "memory")

#define LDSM4(r, addr) \
    asm volatile("ldmatrix.sync.aligned.m8n8.x4.shared.b16 {%0,%1,%2,%3}, [%4];" \
        : "=r"((r)[0]), "=r"((r)[1]), "=r"((r)[2]), "=r"((r)[3]) : "r"(addr))

#define MMA_BF16(d, a, b0v, b1v) \
    asm volatile("mma.sync.aligned.m16n8k16.row.col.f32.bf16.bf16.f32 " \
        "{%0,%1,%2,%3}, {%4,%5,%6,%7}, {%8,%9}, {%0,%1,%2,%3};" \
        : "+f"((d)[0]), "+f"((d)[1]), "+f"((d)[2]), "+f"((d)[3]) \
        : "r"((a)[0]), "r"((a)[1]), "r"((a)[2]), "r"((a)[3]), "r"(b0v), "r"(b1v))

// ---------------- split kernels: fp32 -> (bf16 hi, bf16 lo) ----------------
__device__ __forceinline__ void split4_store(float4 f, __nv_bfloat16* hi, __nv_bfloat16* lo, size_t i2) {
    float fv[4] = {f.x, f.y, f.z, f.w};
    __nv_bfloat16 h[4], l[4];
#pragma unroll
    for (int j = 0; j < 4; j++) {
        h[j] = __float2bfloat16_rn(fv[j]);
        l[j] = __float2bfloat16_rn(fv[j] - __bfloat162float(h[j]));
    }
    ((__nv_bfloat162*)hi)[i2]     = __halves2bfloat162(h[0], h[1]);
    ((__nv_bfloat162*)hi)[i2 + 1] = __halves2bfloat162(h[2], h[3]);
    ((__nv_bfloat162*)lo)[i2]     = __halves2bfloat162(l[0], l[1]);
    ((__nv_bfloat162*)lo)[i2 + 1] = __halves2bfloat162(l[2], l[3]);
}

__global__ void split_x(const float* __restrict__ in, __nv_bfloat16* __restrict__ hi,
                        __nv_bfloat16* __restrict__ lo, int n4) {
    int i = blockIdx.x * blockDim.x + threadIdx.x;
    if (i >= n4) return;
    split4_store(((const float4*)in)[i], hi, lo, (size_t)2 * i);
}

__global__ void split_w(const float* __restrict__ Wq, const float* __restrict__ Wk,
                        const float* __restrict__ Wv, const float* __restrict__ Wo,
                        __nv_bfloat16* __restrict__ hi, __nv_bfloat16* __restrict__ lo) {
    const float* W = blockIdx.y == 0 ? Wq : (blockIdx.y == 1 ? Wk : (blockIdx.y == 2 ? Wv : Wo));
    int i = blockIdx.x * blockDim.x + threadIdx.x;
    size_t base2 = (size_t)blockIdx.y * (DM * (size_t)DM / 2);
    split4_store(((const float4*)W)[i], hi, lo, base2 + 2 * (size_t)i);
}

// ---------------------------------------------------------------------------
// bf16-split tensor-core GEMM via mma.sync: C[M,N] = A[M,K] @ W[N,K]^T
// CTA tile 128x128, BK=64, 3-stage cp.async pipeline, 8 warps (4M x 2N),
// warp tile 32x64. 3 passes per k16: AhBh + AlBh + AhBl, fp32 accum.
// SMEM tile layout per matrix: [128 rows][128B row], SW128 swizzle
//   byte = r*128 + c*16  ->  chunk c' = c ^ (r & 7)
// ---------------------------------------------------------------------------
#define TILE_B  16384                 // 128 x 128B
#define STAGE_B (4 * TILE_B)          // Ah, Al, Bh, Bl
#define NSTAGE  3
#define GEMM_SMEM (NSTAGE * STAGE_B)  // 196608

__global__ __launch_bounds__(256, 1) void gemm_mma(
    const __nv_bfloat16* __restrict__ Ah, const __nv_bfloat16* __restrict__ Al,
    const __nv_bfloat16* __restrict__ Wh, const __nv_bfloat16* __restrict__ Wl,
    int w_off, float* __restrict__ C0, float* __restrict__ C1, float* __restrict__ C2)
{
    extern __shared__ char sm[];
    const int z = blockIdx.z;
    const __nv_bfloat16* Bh = Wh + (size_t)(w_off + z) * DM * DM;
    const __nv_bfloat16* Bl = Wl + (size_t)(w_off + z) * DM * DM;
    float* C = z == 0 ? C0 : (z == 1 ? C1 : C2);

    const uint32_t smem_base = smem_u32(sm);
    const int tid  = threadIdx.x;
    const int lane = tid & 31;
    const int wid  = tid >> 5;
    const int wm   = wid & 3;    // 0..3 -> M offset wm*32
    const int wn   = wid >> 2;   // 0..1 -> N offset wn*64
    const int m0 = blockIdx.y * 128;
    const int n0 = blockIdx.x * 128;

    // ---- per-thread cp.async mapping: 4 chunks per tile (16 total/stage) ----
    uint32_t swo[4]; size_t gA[4], gB[4];
#pragma unroll
    for (int jj = 0; jj < 4; jj++) {
        int q = tid + 256 * jj;       // 0..1023
        int r = q >> 3;               // 0..127
        int c = q & 7;                // 0..7
        swo[jj] = (uint32_t)(r * 128 + ((c ^ (r & 7)) << 4));
        gA[jj] = (size_t)(m0 + r) * DM + c * 8;
        gB[jj] = (size_t)(n0 + r) * DM + c * 8;
    }

    // ---- ldmatrix per-lane address offsets (relative to tile base) ----
    // A (m16k16): lanes 0-15 rows 0..15, lanes 16-31 same rows, k-half 1
    const int arow = lane & 15;           // within 16-row tile
    const int ahalf = lane >> 4;          // k half (0/1)
    const int arm = arow & 7;
    // B (n16k16): lanes 0-7 n0-7/k0-7, 8-15 n0-7/k8-15, 16-23 n8-15/k0-7, 24-31 n8-15/k8-15
    const int brow = ((lane >> 4) << 3) + (lane & 7);
    const int bhalf = (lane >> 3) & 1;
    const int brm = lane & 7;

    // row-base byte offsets (swizzle xor applied at use time via chunk)
    uint32_t aRowOff[2], bRowOff[4];
#pragma unroll
    for (int mi = 0; mi < 2; mi++) aRowOff[mi] = (uint32_t)((wm * 32 + mi * 16 + arow) * 128);
#pragma unroll
    for (int nb = 0; nb < 4; nb++) bRowOff[nb] = (uint32_t)((wn * 64 + nb * 16 + brow) * 128);

    float acc[2][8][4];
#pragma unroll
    for (int mi = 0; mi < 2; mi++)
#pragma unroll
        for (int nt = 0; nt < 8; nt++)
#pragma unroll
            for (int e = 0; e < 4; e++) acc[mi][nt][e] = 0.0f;

    const int ITERS = DM / 64;   // 16

    // issue loads for stage slot = t % NSTAGE, k offset kt = t*64
    auto issue = [&](int t) {
        const uint32_t sb = smem_base + (uint32_t)(t % NSTAGE) * STAGE_B;
        const int kt = t * 64;
#pragma unroll
        for (int jj = 0; jj < 4; jj++) {
            CP16(sb + swo[jj],              (const char*)Ah + (gA[jj] + kt) * 2);
            CP16(sb + TILE_B + swo[jj],     (const char*)Al + (gA[jj] + kt) * 2);
            CP16(sb + 2 * TILE_B + swo[jj], (const char*)Bh + (gB[jj] + kt) * 2);
            CP16(sb + 3 * TILE_B + swo[jj], (const char*)Bl + (gB[jj] + kt) * 2);
        }
        CP_COMMIT();
    };

    issue(0);
    issue(1);

    for (int t = 0; t < ITERS; t++) {
        CP_WAIT1();          // stage t resident
        __syncthreads();     // visible to all; also frees stage (t-1)%3
        if (t + 2 < ITERS) issue(t + 2);

        const uint32_t sb = smem_base + (uint32_t)(t % NSTAGE) * STAGE_B;
        const uint32_t aH = sb, aL = sb + TILE_B, bH = sb + 2 * TILE_B, bL = sb + 3 * TILE_B;

#pragma unroll
        for (int s = 0; s < 4; s++) {              // k16 steps within BK=64
            const uint32_t achunk = (uint32_t)(((2 * s + ahalf) ^ arm) << 4);
            const uint32_t bchunk = (uint32_t)(((2 * s + bhalf) ^ brm) << 4);

            uint32_t fAh[2][4], fAx[2][4], fB[4][4];
#pragma unroll
            for (int mi = 0; mi < 2; mi++) LDSM4(fAh[mi], aH + aRowOff[mi] + achunk);
#pragma unroll
            for (int nb = 0; nb < 4; nb++) LDSM4(fB[nb], bH + bRowOff[nb] + bchunk);
            // pass 1: Ah * Bh
#pragma unroll
            for (int mi = 0; mi < 2; mi++)
#pragma unroll
                for (int nt = 0; nt < 8; nt++)
                    MMA_BF16(acc[mi][nt], fAh[mi], fB[nt >> 1][(nt & 1) * 2], fB[nt >> 1][(nt & 1) * 2 + 1]);
            // pass 2: Al * Bh (reuse fB)
#pragma unroll
            for (int mi = 0; mi < 2; mi++) LDSM4(fAx[mi], aL + aRowOff[mi] + achunk);
#pragma unroll
            for (int mi = 0; mi < 2; mi++)
#pragma unroll
                for (int nt = 0; nt < 8; nt++)
                    MMA_BF16(acc[mi][nt], fAx[mi], fB[nt >> 1][(nt & 1) * 2], fB[nt >> 1][(nt & 1) * 2 + 1]);
            // pass 3: Ah * Bl (reload fB from Bl)
#pragma unroll
            for (int nb = 0; nb < 4; nb++) LDSM4(fB[nb], bL + bRowOff[nb] + bchunk);
#pragma unroll
            for (int mi = 0; mi < 2; mi++)
#pragma unroll
                for (int nt = 0; nt < 8; nt++)
                    MMA_BF16(acc[mi][nt], fAh[mi], fB[nt >> 1][(nt & 1) * 2], fB[nt >> 1][(nt & 1) * 2 + 1]);
        }
    }

    // ---- epilogue: write fp32 C ----
    const int crow0 = m0 + wm * 32 + (lane >> 2);
    const int ccol0 = n0 + wn * 64 + (lane & 3) * 2;
#pragma unroll
    for (int mi = 0; mi < 2; mi++) {
#pragma unroll
        for (int nt = 0; nt < 8; nt++) {
            const int row = crow0 + mi * 16;
            const int col = ccol0 + nt * 8;
            *(float2*)&C[(size_t)row * DM + col]       = make_float2(acc[mi][nt][0], acc[mi][nt][1]);
            *(float2*)&C[(size_t)(row + 8) * DM + col] = make_float2(acc[mi][nt][2], acc[mi][nt][3]);
        }
    }
}

// ---------------- sliding-window attention (validated in R1) ----------------
#define ATT_PAD 68
#define ATT_SMEM_FLOATS (2 * 128 * ATT_PAD + 64 * ATT_PAD)
#define ATT_SMEM_BYTES  (ATT_SMEM_FLOATS * 4)

__global__ void swattn(const float* __restrict__ q, const float* __restrict__ k,
                       const float* __restrict__ v, float* __restrict__ o)
{
    extern __shared__ float smf[];
    float* Ks = smf;
    float* Vs = smf + 128 * ATT_PAD;
    float* Ss = smf + 2 * 128 * ATT_PAD;

    const int qstart  = blockIdx.x * 64;
    const int h       = blockIdx.y;
    const int korigin = qstart - (WIN - 1);
    const int hcol    = h * HD;

    const int tid = threadIdx.x;
    const int qi  = tid & 63;
    const int hv  = tid >> 6;

    for (int i = tid; i < 128 * 16; i += 128) {
        const int r  = i >> 4;
        const int c4 = (i & 15) << 2;
        const int g  = korigin + r;
        float4 kk = make_float4(0.f, 0.f, 0.f, 0.f);
        float4 vv = kk;
        if (g >= 0 && g < S_LEN) {
            kk = *(const float4*)&k[(size_t)g * DM + hcol + c4];
            vv = *(const float4*)&v[(size_t)g * DM + hcol + c4];
        }
        *(float4*)&Ks[r * ATT_PAD + c4] = kk;
        *(float4*)&Vs[r * ATT_PAD + c4] = vv;
    }

    float qreg[64];
    {
        const float* qrow = &q[(size_t)(qstart + qi) * DM + hcol];
#pragma unroll
        for (int j = 0; j < 16; j++) {
            float4 t4 = *(const float4*)&qrow[4 * j];
            qreg[4*j+0] = t4.x * 0.125f;
            qreg[4*j+1] = t4.y * 0.125f;
            qreg[4*j+2] = t4.z * 0.125f;
            qreg[4*j+3] = t4.w * 0.125f;
        }
    }
    __syncthreads();

#pragma unroll 4
    for (int w = hv * 32; w < hv * 32 + 32; w++) {
        const int r = qi + w;
        const float* kr = &Ks[r * ATT_PAD];
        float s = 0.0f;
#pragma unroll
        for (int d = 0; d < 64; d += 4) {
            float4 kk = *(const float4*)&kr[d];
            s = fmaf(qreg[d+0], kk.x, s);
            s = fmaf(qreg[d+1], kk.y, s);
            s = fmaf(qreg[d+2], kk.z, s);
            s = fmaf(qreg[d+3], kk.w, s);
        }
        const int gkey = korigin + r;
        Ss[qi * ATT_PAD + w] = (gkey >= 0) ? s : -INFINITY;
    }
    __syncthreads();

    float p[64];
    float mx = -INFINITY;
#pragma unroll
    for (int w = 0; w < 64; w++) { p[w] = Ss[qi * ATT_PAD + w]; mx = fmaxf(mx, p[w]); }
    float sum = 0.0f;
#pragma unroll
    for (int w = 0; w < 64; w++) { p[w] = __expf(p[w] - mx); sum += p[w]; }
    const float inv = 1.0f / sum;
#pragma unroll
    for (int w = 0; w < 64; w++) p[w] *= inv;

    float accv[32];
#pragma unroll
    for (int d = 0; d < 32; d++) accv[d] = 0.0f;

    const int dbase = hv * 32;
    for (int w = 0; w < 64; w++) {
        const float pw = p[w];
        const float* vr = &Vs[(qi + w) * ATT_PAD + dbase];
#pragma unroll
        for (int d4 = 0; d4 < 8; d4++) {
            float4 vv = *(const float4*)&vr[4 * d4];
            accv[4*d4+0] = fmaf(pw, vv.x, accv[4*d4+0]);
            accv[4*d4+1] = fmaf(pw, vv.y, accv[4*d4+1]);
            accv[4*d4+2] = fmaf(pw, vv.z, accv[4*d4+2]);
            accv[4*d4+3] = fmaf(pw, vv.w, accv[4*d4+3]);
        }
    }

    float* orow = &o[(size_t)(qstart + qi) * DM + hcol + dbase];
#pragma unroll
    for (int d4 = 0; d4 < 8; d4++)
        *(float4*)&orow[4 * d4] =
            make_float4(accv[4*d4+0], accv[4*d4+1], accv[4*d4+2], accv[4*d4+3]);
}

// ---------------- launch ----------------
extern "C" void kernel_launch(void* const* d_in, const int* in_sizes, int n_in,
                              void* d_out, int out_size)
{
    const float* x  = (const float*)d_in[0];
    const float* Wq = (const float*)d_in[1];
    const float* Wk = (const float*)d_in[2];
    const float* Wv = (const float*)d_in[3];
    const float* Wo = (const float*)d_in[4];
    float* out = (float*)d_out;

    float *qp, *kp, *vp, *aop;
    __nv_bfloat16 *xh, *xl, *wh, *wl, *aoh, *aol;
    cudaGetSymbolAddress((void**)&qp,  g_q);
    cudaGetSymbolAddress((void**)&kp,  g_k);
    cudaGetSymbolAddress((void**)&vp,  g_v);
    cudaGetSymbolAddress((void**)&aop, g_ao);
    cudaGetSymbolAddress((void**)&xh,  g_xh);
    cudaGetSymbolAddress((void**)&xl,  g_xl);
    cudaGetSymbolAddress((void**)&wh,  g_wh);
    cudaGetSymbolAddress((void**)&wl,  g_wl);
    cudaGetSymbolAddress((void**)&aoh, g_aoh);
    cudaGetSymbolAddress((void**)&aol, g_aol);

    cudaFuncSetAttribute(gemm_mma, cudaFuncAttributeMaxDynamicSharedMemorySize, GEMM_SMEM);
    cudaFuncSetAttribute(swattn,   cudaFuncAttributeMaxDynamicSharedMemorySize, ATT_SMEM_BYTES);

    // 1. split inputs and weights into bf16 hi/lo
    split_x<<<(S_LEN * DM / 4 + 255) / 256, 256>>>(x, xh, xl, S_LEN * DM / 4);
    split_w<<<dim3(DM * DM / 4 / 256, 4), 256>>>(Wq, Wk, Wv, Wo, wh, wl);

    // 2. QKV projections (fused via grid.z)
    gemm_mma<<<dim3(DM / 128, S_LEN / 128, 3), 256, GEMM_SMEM>>>(xh, xl, wh, wl, 0, qp, kp, vp);

    // 3. sliding-window attention
    swattn<<<dim3(S_LEN / 64, NH), 128, ATT_SMEM_BYTES>>>(qp, kp, vp, aop);

    // 4. split attention output, then output projection
    split_x<<<(S_LEN * DM / 4 + 255) / 256, 256>>>(aop, aoh, aol, S_LEN * DM / 4);
    gemm_mma<<<dim3(DM / 128, S_LEN / 128, 1), 256, GEMM_SMEM>>>(aoh, aol, wh, wl, 3, out, out, out);
}

// round 4
// speedup vs baseline: 2.2081x; 1.0123x over previous
#include <cuda_runtime.h>
#include <cuda_bf16.h>
#include <cstdint>
#include <math.h>

#define S_LEN 4096
#define DM    1024
#define NH    16
#define HD    64
#define WIN   64

// ---------------- device scratch (no allocations allowed) ----------------
__device__ float g_q  [S_LEN * DM];
__device__ float g_k  [S_LEN * DM];
__device__ float g_v  [S_LEN * DM];
__device__ float g_xr [S_LEN * DM];      // tf32-rounded x
__device__ float g_wr [4 * DM * DM];     // tf32-rounded Wq,Wk,Wv,Wo
__device__ float g_aor[S_LEN * DM];      // tf32-rounded attention output

// ---------------- PTX helpers (baseline sm_80+ features only) ----------------
__device__ __forceinline__ uint32_t smem_u32(const void* p) {
    uint32_t a;
    asm("{ .reg .u64 t; cvta.to.shared.u64 t, %1; cvt.u32.u64 %0, t; }" : "=r"(a) : "l"(p));
    return a;
}
#define CP16(dst, src) \
    asm volatile("cp.async.cg.shared.global [%0], [%1], 16;" :: "r"((uint32_t)(dst)), "l"(src) : "memory")
#define CP_COMMIT() asm volatile("cp.async.commit_group;" ::: "memory")
#define CP_WAIT2()  asm volatile("cp.async.wait_group 2;" ::: "memory")

#define LDSM4(r, addr) \
    asm volatile("ldmatrix.sync.aligned.m8n8.x4.shared.b16 {%0,%1,%2,%3}, [%4];" \
        : "=r"((r)[0]), "=r"((r)[1]), "=r"((r)[2]), "=r"((r)[3]) : "r"(addr))

#define MMA_TF32(d, a, b0v, b1v) \
    asm volatile("mma.sync.aligned.m16n8k8.row.col.f32.tf32.tf32.f32 " \
        "{%0,%1,%2,%3}, {%4,%5,%6,%7}, {%8,%9}, {%0,%1,%2,%3};" \
        : "+f"((d)[0]), "+f"((d)[1]), "+f"((d)[2]), "+f"((d)[3]) \
        : "r"((a)[0]), "r"((a)[1]), "r"((a)[2]), "r"((a)[3]), "r"(b0v), "r"(b1v))

__device__ __forceinline__ float tf32_rna(float x) {
    uint32_t t;
    asm("cvt.rna.tf32.f32 %0, %1;" : "=r"(t) : "f"(x));
    return __uint_as_float(t);
}

// ---------------- tf32 pre-round kernels ----------------
__global__ void round_x(const float* __restrict__ in, float* __restrict__ out, int n4) {
    int i = blockIdx.x * blockDim.x + threadIdx.x;
    if (i >= n4) return;
    float4 f = ((const float4*)in)[i];
    ((float4*)out)[i] = make_float4(tf32_rna(f.x), tf32_rna(f.y), tf32_rna(f.z), tf32_rna(f.w));
}

__global__ void round_w(const float* __restrict__ Wq, const float* __restrict__ Wk,
                        const float* __restrict__ Wv, const float* __restrict__ Wo,
                        float* __restrict__ out) {
    const float* W = blockIdx.y == 0 ? Wq : (blockIdx.y == 1 ? Wk : (blockIdx.y == 2 ? Wv : Wo));
    int i = blockIdx.x * blockDim.x + threadIdx.x;   // chunks of DM*DM/4
    float4 f = ((const float4*)W)[i];
    ((float4*)(out + (size_t)blockIdx.y * DM * DM))[i] =
        make_float4(tf32_rna(f.x), tf32_rna(f.y), tf32_rna(f.z), tf32_rna(f.w));
}

// ---------------------------------------------------------------------------
// tf32 tensor-core GEMM: C[M,N] = A[M,K] @ W[N,K]^T   (A, W pre-rounded tf32)
// CTA 128x128, BK=32 (128B rows), 4-stage cp.async, 8 warps (4M x 2N),
// warp tile 32x64, mma.m16n8k8.tf32.  SW128 swizzle: chunk c' = c ^ (r&7).
// Fragments loaded via ldmatrix on fp32-as-b16 (8x4 fp32 tile == 8x8 b16).
// ---------------------------------------------------------------------------
#define TILE_B  16384                 // 128 rows x 128B (32 fp32)
#define STAGE_B (2 * TILE_B)          // A + B
#define NSTAGE  4
#define GEMM_SMEM (NSTAGE * STAGE_B)  // 131072

__global__ __launch_bounds__(256, 1) void gemm_tf32(
    const float* __restrict__ A, const float* __restrict__ Wr,
    int w_off, float* __restrict__ C0, float* __restrict__ C1, float* __restrict__ C2)
{
    extern __shared__ char sm[];
    const int z = blockIdx.z;
    const float* B = Wr + (size_t)(w_off + z) * DM * DM;
    float* C = z == 0 ? C0 : (z == 1 ? C1 : C2);

    const uint32_t smem_base = smem_u32(sm);
    const int tid  = threadIdx.x;
    const int lane = tid & 31;
    const int wid  = tid >> 5;
    const int wm   = wid & 3;
    const int wn   = wid >> 2;
    const int m0 = blockIdx.y * 128;
    const int n0 = blockIdx.x * 128;

    // cp.async mapping: 4 16B chunks per thread per tile
    uint32_t swo[4]; size_t gA[4], gB[4];
#pragma unroll
    for (int jj = 0; jj < 4; jj++) {
        int q = tid + 256 * jj;
        int r = q >> 3, c = q & 7;
        swo[jj] = (uint32_t)(r * 128 + ((c ^ (r & 7)) << 4));
        gA[jj] = (size_t)(m0 + r) * DM + c * 4;
        gB[jj] = (size_t)(n0 + r) * DM + c * 4;
    }

    // ldmatrix addressing: matrix idx lm = lane>>3, row-in-matrix = lane&7
    const int lm   = lane >> 3;
    const int lrow = lane & 7;
    const int cSel = lm >> 1;           // chunk parity (k lo/hi 4-float group)
    uint32_t aOff[2]; int aXor[2];
#pragma unroll
    for (int mi = 0; mi < 2; mi++) {
        int ar = wm * 32 + mi * 16 + (lm & 1) * 8 + lrow;
        aOff[mi] = (uint32_t)(ar * 128); aXor[mi] = ar & 7;
    }
    uint32_t bOff[4]; int bXor[4];
#pragma unroll
    for (int pb = 0; pb < 4; pb++) {
        int br = wn * 64 + pb * 16 + (lm & 1) * 8 + lrow;
        bOff[pb] = (uint32_t)(br * 128); bXor[pb] = br & 7;
    }

    float acc[2][8][4];
#pragma unroll
    for (int mi = 0; mi < 2; mi++)
#pragma unroll
        for (int nb = 0; nb < 8; nb++)
#pragma unroll
            for (int e = 0; e < 4; e++) acc[mi][nb][e] = 0.0f;

    const int ITERS = DM / 32;   // 32

    auto issue = [&](int t) {
        const uint32_t sb = smem_base + (uint32_t)(t % NSTAGE) * STAGE_B;
        const int kt = t * 32;
#pragma unroll
        for (int jj = 0; jj < 4; jj++) {
            CP16(sb + swo[jj],          (const char*)A + (gA[jj] + kt) * 4);
            CP16(sb + TILE_B + swo[jj], (const char*)B + (gB[jj] + kt) * 4);
        }
        CP_COMMIT();
    };

    issue(0); issue(1); issue(2);

    for (int t = 0; t < ITERS; t++) {
        CP_WAIT2();
        __syncthreads();
        if (t + 3 < ITERS) issue(t + 3);

        const uint32_t sb = smem_base + (uint32_t)(t % NSTAGE) * STAGE_B;
        const uint32_t aBase = sb, bBase = sb + TILE_B;

#pragma unroll
        for (int s = 0; s < 4; s++) {          // four k8 steps in BK=32
            uint32_t fA[2][4];
#pragma unroll
            for (int mi = 0; mi < 2; mi++)
                LDSM4(fA[mi], aBase + aOff[mi] + (uint32_t)((((2 * s) + cSel) ^ aXor[mi]) << 4));
            uint32_t fB[8][2];
#pragma unroll
            for (int pb = 0; pb < 4; pb++) {
                uint32_t bt[4];
                LDSM4(bt, bBase + bOff[pb] + (uint32_t)((((2 * s) + cSel) ^ bXor[pb]) << 4));
                fB[2 * pb][0] = bt[0]; fB[2 * pb][1] = bt[2];
                fB[2 * pb + 1][0] = bt[1]; fB[2 * pb + 1][1] = bt[3];
            }
#pragma unroll
            for (int mi = 0; mi < 2; mi++)
#pragma unroll
                for (int nb = 0; nb < 8; nb++)
                    MMA_TF32(acc[mi][nb], fA[mi], fB[nb][0], fB[nb][1]);
        }
    }

    // epilogue
    const int crow0 = m0 + wm * 32 + (lane >> 2);
    const int ccol0 = n0 + wn * 64 + (lane & 3) * 2;
#pragma unroll
    for (int mi = 0; mi < 2; mi++) {
#pragma unroll
        for (int nb = 0; nb < 8; nb++) {
            const int row = crow0 + mi * 16;
            const int col = ccol0 + nb * 8;
            *(float2*)&C[(size_t)row * DM + col]       = make_float2(acc[mi][nb][0], acc[mi][nb][1]);
            *(float2*)&C[(size_t)(row + 8) * DM + col] = make_float2(acc[mi][nb][2], acc[mi][nb][3]);
        }
    }
}

// ---------------------------------------------------------------------------
// Sliding-window attention v2.
// Block = 64 queries x 1 head, 128 threads; thread (qi = tid>>1, hv = tid&1).
// QK: hv splits the window (32 w each), 4 independent accumulators per score.
// Softmax stats + p-value exchange via shfl_xor(1) (pairs are adjacent lanes).
// AV: hv splits head dim (32 each). Output written tf32-rounded (GEMM input).
// smem: K[127][68] + V[127][68] = 69 KB -> 3 CTAs/SM.
// ---------------------------------------------------------------------------
#define ATT_PAD 68
#define ATT_ROWS 127
#define ATT_SMEM_BYTES (2 * ATT_ROWS * ATT_PAD * 4)

__global__ __launch_bounds__(128, 3) void swattn(
    const float* __restrict__ q, const float* __restrict__ k,
    const float* __restrict__ v, float* __restrict__ o)
{
    extern __shared__ float smf[];
    float* Ks = smf;
    float* Vs = smf + ATT_ROWS * ATT_PAD;

    const int qstart  = blockIdx.x * 64;
    const int h       = blockIdx.y;
    const int korigin = qstart - (WIN - 1);
    const int hcol    = h * HD;

    const int tid = threadIdx.x;
    const int qi  = tid >> 1;
    const int hv  = tid & 1;

    // load K,V tiles (127 rows x 64 cols), zero-filled out of range
    for (int i = tid; i < ATT_ROWS * 16; i += 128) {
        const int r  = i >> 4;
        const int c4 = (i & 15) << 2;
        const int g  = korigin + r;
        float4 kk = make_float4(0.f, 0.f, 0.f, 0.f);
        float4 vv = kk;
        if (g >= 0) {
            kk = *(const float4*)&k[(size_t)g * DM + hcol + c4];
            vv = *(const float4*)&v[(size_t)g * DM + hcol + c4];
        }
        *(float4*)&Ks[r * ATT_PAD + c4] = kk;
        *(float4*)&Vs[r * ATT_PAD + c4] = vv;
    }

    // q row into regs, pre-scaled
    float qreg[64];
    {
        const float* qrow = &q[(size_t)(qstart + qi) * DM + hcol];
#pragma unroll
        for (int j = 0; j < 16; j++) {
            float4 t4 = *(const float4*)&qrow[4 * j];
            qreg[4*j+0] = t4.x * 0.125f;
            qreg[4*j+1] = t4.y * 0.125f;
            qreg[4*j+2] = t4.z * 0.125f;
            qreg[4*j+3] = t4.w * 0.125f;
        }
    }
    __syncthreads();

    // scores for own half of the window (4 independent FMA chains)
    float p[32];
#pragma unroll 2
    for (int wl = 0; wl < 32; wl++) {
        const int r = qi + hv * 32 + wl;
        const float* kr = &Ks[r * ATT_PAD];
        float s0 = 0.f, s1 = 0.f, s2 = 0.f, s3 = 0.f;
#pragma unroll
        for (int d = 0; d < 64; d += 16) {
            float4 k0 = *(const float4*)&kr[d];
            float4 k1 = *(const float4*)&kr[d + 4];
            float4 k2 = *(const float4*)&kr[d + 8];
            float4 k3 = *(const float4*)&kr[d + 12];
            s0 = fmaf(qreg[d+0],  k0.x, s0); s0 = fmaf(qreg[d+1],  k0.y, s0);
            s0 = fmaf(qreg[d+2],  k0.z, s0); s0 = fmaf(qreg[d+3],  k0.w, s0);
            s1 = fmaf(qreg[d+4],  k1.x, s1); s1 = fmaf(qreg[d+5],  k1.y, s1);
            s1 = fmaf(qreg[d+6],  k1.z, s1); s1 = fmaf(qreg[d+7],  k1.w, s1);
            s2 = fmaf(qreg[d+8],  k2.x, s2); s2 = fmaf(qreg[d+9],  k2.y, s2);
            s2 = fmaf(qreg[d+10], k2.z, s2); s2 = fmaf(qreg[d+11], k2.w, s2);
            s3 = fmaf(qreg[d+12], k3.x, s3); s3 = fmaf(qreg[d+13], k3.y, s3);
            s3 = fmaf(qreg[d+14], k3.z, s3); s3 = fmaf(qreg[d+15], k3.w, s3);
        }
        const float s = (s0 + s1) + (s2 + s3);
        p[wl] = (korigin + r >= 0) ? s : -INFINITY;
    }

    // softmax across both halves via pair shuffle
    float mx = -INFINITY;
#pragma unroll
    for (int wl = 0; wl < 32; wl++) mx = fmaxf(mx, p[wl]);
    mx = fmaxf(mx, __shfl_xor_sync(0xffffffffu, mx, 1));
    float sum = 0.0f;
#pragma unroll
    for (int wl = 0; wl < 32; wl++) { p[wl] = __expf(p[wl] - mx); sum += p[wl]; }
    sum += __shfl_xor_sync(0xffffffffu, sum, 1);
    const float inv = 1.0f / sum;
#pragma unroll
    for (int wl = 0; wl < 32; wl++) p[wl] *= inv;

    // AV: own 32 head dims over all 64 window positions
    float accv[32];
#pragma unroll
    for (int d = 0; d < 32; d++) accv[d] = 0.0f;

    const int dbase = hv * 32;
#pragma unroll
    for (int w = 0; w < 64; w++) {
        const float own = p[w & 31];
        const float other = __shfl_xor_sync(0xffffffffu, own, 1);
        const float pw = ((w >> 5) == hv) ? own : other;
        const float* vr = &Vs[(qi + w) * ATT_PAD + dbase];
#pragma unroll
        for (int d4 = 0; d4 < 8; d4++) {
            float4 vv = *(const float4*)&vr[4 * d4];
            accv[4*d4+0] = fmaf(pw, vv.x, accv[4*d4+0]);
            accv[4*d4+1] = fmaf(pw, vv.y, accv[4*d4+1]);
            accv[4*d4+2] = fmaf(pw, vv.z, accv[4*d4+2]);
            accv[4*d4+3] = fmaf(pw, vv.w, accv[4*d4+3]);
        }
    }

    // write tf32-rounded output (feeds the Wo tf32 GEMM directly)
    float* orow = &o[(size_t)(qstart + qi) * DM + hcol + dbase];
#pragma unroll
    for (int d4 = 0; d4 < 8; d4++)
        *(float4*)&orow[4 * d4] = make_float4(
            tf32_rna(accv[4*d4+0]), tf32_rna(accv[4*d4+1]),
            tf32_rna(accv[4*d4+2]), tf32_rna(accv[4*d4+3]));
}

// ---------------- launch ----------------
extern "C" void kernel_launch(void* const* d_in, const int* in_sizes, int n_in,
                              void* d_out, int out_size)
{
    const float* x  = (const float*)d_in[0];
    const float* Wq = (const float*)d_in[1];
    const float* Wk = (const float*)d_in[2];
    const float* Wv = (const float*)d_in[3];
    const float* Wo = (const float*)d_in[4];
    float* out = (float*)d_out;

    float *qp, *kp, *vp, *xr, *wr, *aor;
    cudaGetSymbolAddress((void**)&qp,  g_q);
    cudaGetSymbolAddress((void**)&kp,  g_k);
    cudaGetSymbolAddress((void**)&vp,  g_v);
    cudaGetSymbolAddress((void**)&xr,  g_xr);
    cudaGetSymbolAddress((void**)&wr,  g_wr);
    cudaGetSymbolAddress((void**)&aor, g_aor);

    cudaFuncSetAttribute(gemm_tf32, cudaFuncAttributeMaxDynamicSharedMemorySize, GEMM_SMEM);
    cudaFuncSetAttribute(swattn,    cudaFuncAttributeMaxDynamicSharedMemorySize, ATT_SMEM_BYTES);

    // 1. pre-round x and W to tf32 (exact truncation inside the MMA)
    round_x<<<(S_LEN * DM / 4 + 255) / 256, 256>>>(x, xr, S_LEN * DM / 4);
    round_w<<<dim3(DM * DM / 4 / 256, 4), 256>>>(Wq, Wk, Wv, Wo, wr);

    // 2. QKV projections (fused via grid.z)
    gemm_tf32<<<dim3(DM / 128, S_LEN / 128, 3), 256, GEMM_SMEM>>>(xr, wr, 0, qp, kp, vp);

    // 3. sliding-window attention (emits tf32-rounded output)
    swattn<<<dim3(S_LEN / 64, NH), 128, ATT_SMEM_BYTES>>>(qp, kp, vp, aor);

    // 4. output projection
    gemm_tf32<<<dim3(DM / 128, S_LEN / 128, 1), 256, GEMM_SMEM>>>(aor, wr, 3, out, out, out);
}

// round 5
// speedup vs baseline: 2.2988x; 1.0411x over previous
#include <cuda_runtime.h>
#include <cuda_bf16.h>
#include <cstdint>
#include <math.h>

#define S_LEN 4096
#define DM    1024
#define NH    16
#define HD    64
#define WIN   64

// ---------------- device scratch (no allocations allowed) ----------------
__device__ float g_q  [S_LEN * DM];
__device__ float g_k  [S_LEN * DM];
__device__ float g_v  [S_LEN * DM];
__device__ float g_xr [S_LEN * DM];      // tf32-rounded x
__device__ float g_wr [4 * DM * DM];     // tf32-rounded Wq,Wk,Wv,Wo
__device__ float g_aor[S_LEN * DM];      // tf32-rounded attention output

// ---------------- PTX helpers ----------------
__device__ __forceinline__ uint32_t smem_u32(const void* p) {
    uint32_t a;
    asm("{ .reg .u64 t; cvta.to.shared.u64 t, %1; cvt.u32.u64 %0, t; }" : "=r"(a) : "l"(p));
    return a;
}
#define CP16(dst, src) \
    asm volatile("cp.async.cg.shared.global [%0], [%1], 16;" :: "r"((uint32_t)(dst)), "l"(src) : "memory")
#define CP_COMMIT() asm volatile("cp.async.commit_group;" ::: "memory")
#define CP_WAIT2()  asm volatile("cp.async.wait_group 2;" ::: "memory")

#define LDSM4(r, addr) \
    asm volatile("ldmatrix.sync.aligned.m8n8.x4.shared.b16 {%0,%1,%2,%3}, [%4];" \
        : "=r"((r)[0]), "=r"((r)[1]), "=r"((r)[2]), "=r"((r)[3]) : "r"(addr))

#define MMA_TF32(d, a, b0v, b1v) \
    asm volatile("mma.sync.aligned.m16n8k8.row.col.f32.tf32.tf32.f32 " \
        "{%0,%1,%2,%3}, {%4,%5,%6,%7}, {%8,%9}, {%0,%1,%2,%3};" \
        : "+f"((d)[0]), "+f"((d)[1]), "+f"((d)[2]), "+f"((d)[3]) \
        : "r"((a)[0]), "r"((a)[1]), "r"((a)[2]), "r"((a)[3]), "r"(b0v), "r"(b1v))

__device__ __forceinline__ float tf32_rna(float x) {
    uint32_t t;
    asm("cvt.rna.tf32.f32 %0, %1;" : "=r"(t) : "f"(x));
    return __uint_as_float(t);
}

// ---------------- tf32 pre-round kernels ----------------
__global__ void round_x(const float* __restrict__ in, float* __restrict__ out, int n4) {
    int i = blockIdx.x * blockDim.x + threadIdx.x;
    if (i >= n4) return;
    float4 f = ((const float4*)in)[i];
    ((float4*)out)[i] = make_float4(tf32_rna(f.x), tf32_rna(f.y), tf32_rna(f.z), tf32_rna(f.w));
}

__global__ void round_w(const float* __restrict__ Wq, const float* __restrict__ Wk,
                        const float* __restrict__ Wv, const float* __restrict__ Wo,
                        float* __restrict__ out) {
    const float* W = blockIdx.y == 0 ? Wq : (blockIdx.y == 1 ? Wk : (blockIdx.y == 2 ? Wv : Wo));
    int i = blockIdx.x * blockDim.x + threadIdx.x;
    float4 f = ((const float4*)W)[i];
    ((float4*)(out + (size_t)blockIdx.y * DM * DM))[i] =
        make_float4(tf32_rna(f.x), tf32_rna(f.y), tf32_rna(f.z), tf32_rna(f.w));
}

// ---------------------------------------------------------------------------
// tf32 GEMM v2: C[M,N] = A[M,K] @ W[N,K]^T
// CTA 128x128, BK=32, 4-stage cp.async, 4 warps in 2x2 grid, warp tile 64x64.
// Per k8 step per warp: 4 ldsm.x4 (A) + 4 ldsm.x4 (B) -> 32 MMAs (8 MAC/byte).
// ---------------------------------------------------------------------------
#define TILE_B  16384                 // 128 rows x 128B (32 fp32)
#define STAGE_B (2 * TILE_B)
#define NSTAGE  4
#define GEMM_SMEM (NSTAGE * STAGE_B)  // 131072

__global__ __launch_bounds__(128, 1) void gemm_tf32(
    const float* __restrict__ A, const float* __restrict__ Wr,
    int w_off, float* __restrict__ C0, float* __restrict__ C1, float* __restrict__ C2)
{
    extern __shared__ char sm[];
    const int z = blockIdx.z;
    const float* B = Wr + (size_t)(w_off + z) * DM * DM;
    float* C = z == 0 ? C0 : (z == 1 ? C1 : C2);

    const uint32_t smem_base = smem_u32(sm);
    const int tid  = threadIdx.x;
    const int lane = tid & 31;
    const int wid  = tid >> 5;
    const int wm   = wid & 1;    // M offset wm*64
    const int wn   = wid >> 1;   // N offset wn*64
    const int m0 = blockIdx.y * 128;
    const int n0 = blockIdx.x * 128;

    // cp.async mapping: 8 16B chunks per thread per tile (128 rows x 8 chunks)
    uint32_t swo[8], gA[8], gB[8];
#pragma unroll
    for (int jj = 0; jj < 8; jj++) {
        int q = tid + 128 * jj;
        int r = q >> 3, c = q & 7;
        swo[jj] = (uint32_t)(r * 128 + ((c ^ (r & 7)) << 4));
        gA[jj] = (uint32_t)((m0 + r) * DM + c * 4);
        gB[jj] = (uint32_t)((n0 + r) * DM + c * 4);
    }

    // ldmatrix addressing
    const int lm   = lane >> 3;
    const int lrow = lane & 7;
    const int cSel = lm >> 1;
    uint32_t aOff[4]; int aXor[4];
#pragma unroll
    for (int mi = 0; mi < 4; mi++) {
        int ar = wm * 64 + mi * 16 + (lm & 1) * 8 + lrow;
        aOff[mi] = (uint32_t)(ar * 128); aXor[mi] = ar & 7;
    }
    uint32_t bOff[4]; int bXor[4];
#pragma unroll
    for (int pb = 0; pb < 4; pb++) {
        int br = wn * 64 + pb * 16 + (lm & 1) * 8 + lrow;
        bOff[pb] = (uint32_t)(br * 128); bXor[pb] = br & 7;
    }

    float acc[4][8][4];
#pragma unroll
    for (int mi = 0; mi < 4; mi++)
#pragma unroll
        for (int nb = 0; nb < 8; nb++)
#pragma unroll
            for (int e = 0; e < 4; e++) acc[mi][nb][e] = 0.0f;

    const int ITERS = DM / 32;   // 32

    auto issue = [&](int t) {
        const uint32_t sb = smem_base + (uint32_t)(t % NSTAGE) * STAGE_B;
        const uint32_t kt = (uint32_t)(t * 32);
#pragma unroll
        for (int jj = 0; jj < 8; jj++) {
            CP16(sb + swo[jj],          (const char*)A + (size_t)(gA[jj] + kt) * 4);
            CP16(sb + TILE_B + swo[jj], (const char*)B + (size_t)(gB[jj] + kt) * 4);
        }
        CP_COMMIT();
    };

    issue(0); issue(1); issue(2);

    for (int t = 0; t < ITERS; t++) {
        CP_WAIT2();
        __syncthreads();
        if (t + 3 < ITERS) issue(t + 3);

        const uint32_t sb = smem_base + (uint32_t)(t % NSTAGE) * STAGE_B;
        const uint32_t aBase = sb, bBase = sb + TILE_B;

#pragma unroll
        for (int s = 0; s < 4; s++) {
            uint32_t fA[4][4];
#pragma unroll
            for (int mi = 0; mi < 4; mi++)
                LDSM4(fA[mi], aBase + aOff[mi] + (uint32_t)((((2 * s) + cSel) ^ aXor[mi]) << 4));
            uint32_t fB[8][2];
#pragma unroll
            for (int pb = 0; pb < 4; pb++) {
                uint32_t bt[4];
                LDSM4(bt, bBase + bOff[pb] + (uint32_t)((((2 * s) + cSel) ^ bXor[pb]) << 4));
                fB[2 * pb][0] = bt[0]; fB[2 * pb][1] = bt[2];
                fB[2 * pb + 1][0] = bt[1]; fB[2 * pb + 1][1] = bt[3];
            }
#pragma unroll
            for (int mi = 0; mi < 4; mi++)
#pragma unroll
                for (int nb = 0; nb < 8; nb++)
                    MMA_TF32(acc[mi][nb], fA[mi], fB[nb][0], fB[nb][1]);
        }
    }

    // epilogue
    const int crow0 = m0 + wm * 64 + (lane >> 2);
    const int ccol0 = n0 + wn * 64 + (lane & 3) * 2;
#pragma unroll
    for (int mi = 0; mi < 4; mi++) {
#pragma unroll
        for (int nb = 0; nb < 8; nb++) {
            const int row = crow0 + mi * 16;
            const int col = ccol0 + nb * 8;
            *(float2*)&C[(size_t)row * DM + col]       = make_float2(acc[mi][nb][0], acc[mi][nb][1]);
            *(float2*)&C[(size_t)(row + 8) * DM + col] = make_float2(acc[mi][nb][2], acc[mi][nb][3]);
        }
    }
}

// ---------------------------------------------------------------------------
// Sliding-window attention v3.
// Block = 64 queries x 1 head, 128 threads: qi = tid&63 (lanes = consecutive
// queries -> consecutive smem rows -> conflict-free LDS.128), hv = tid>>6.
// QK: hv splits the window, 4 independent accumulators. Scores buffered in
// regs, exchanged through smem overlaid on the dead K tile (3 CTAs/SM at 69KB).
// AV: hv splits head dim. Output tf32-rounded (feeds Wo GEMM directly).
// ---------------------------------------------------------------------------
#define ATT_PAD 68
#define ATT_ROWS 127
#define ATT_SMEM_BYTES (2 * ATT_ROWS * ATT_PAD * 4)   // 69088

__global__ __launch_bounds__(128, 3) void swattn(
    const float* __restrict__ q, const float* __restrict__ k,
    const float* __restrict__ v, float* __restrict__ o)
{
    extern __shared__ float smf[];
    float* Ks = smf;
    float* Vs = smf + ATT_ROWS * ATT_PAD;
    float* Ss = smf;   // overlaid on K tile after QK phase (64x68 <= 127x68)

    const int qstart  = blockIdx.x * 64;
    const int h       = blockIdx.y;
    const int korigin = qstart - (WIN - 1);
    const int hcol    = h * HD;

    const int tid = threadIdx.x;
    const int qi  = tid & 63;
    const int hv  = tid >> 6;

    // load K,V tiles (127 rows x 64 cols), zero-filled out of range
    for (int i = tid; i < ATT_ROWS * 16; i += 128) {
        const int r  = i >> 4;
        const int c4 = (i & 15) << 2;
        const int g  = korigin + r;
        float4 kk = make_float4(0.f, 0.f, 0.f, 0.f);
        float4 vv = kk;
        if (g >= 0) {
            kk = *(const float4*)&k[(size_t)g * DM + hcol + c4];
            vv = *(const float4*)&v[(size_t)g * DM + hcol + c4];
        }
        *(float4*)&Ks[r * ATT_PAD + c4] = kk;
        *(float4*)&Vs[r * ATT_PAD + c4] = vv;
    }

    // q row into regs, pre-scaled by 1/sqrt(hd)
    float qreg[64];
    {
        const float* qrow = &q[(size_t)(qstart + qi) * DM + hcol];
#pragma unroll
        for (int j = 0; j < 16; j++) {
            float4 t4 = *(const float4*)&qrow[4 * j];
            qreg[4*j+0] = t4.x * 0.125f;
            qreg[4*j+1] = t4.y * 0.125f;
            qreg[4*j+2] = t4.z * 0.125f;
            qreg[4*j+3] = t4.w * 0.125f;
        }
    }
    __syncthreads();

    // QK: own half of the window, 4 independent FMA chains per score
    float sreg[32];
#pragma unroll 2
    for (int wl = 0; wl < 32; wl++) {
        const int r = qi + hv * 32 + wl;
        const float* kr = &Ks[r * ATT_PAD];
        float s0 = 0.f, s1 = 0.f, s2 = 0.f, s3 = 0.f;
#pragma unroll
        for (int d = 0; d < 64; d += 16) {
            float4 k0 = *(const float4*)&kr[d];
            float4 k1 = *(const float4*)&kr[d + 4];
            float4 k2 = *(const float4*)&kr[d + 8];
            float4 k3 = *(const float4*)&kr[d + 12];
            s0 = fmaf(qreg[d+0],  k0.x, s0); s0 = fmaf(qreg[d+1],  k0.y, s0);
            s0 = fmaf(qreg[d+2],  k0.z, s0); s0 = fmaf(qreg[d+3],  k0.w, s0);
            s1 = fmaf(qreg[d+4],  k1.x, s1); s1 = fmaf(qreg[d+5],  k1.y, s1);
            s1 = fmaf(qreg[d+6],  k1.z, s1); s1 = fmaf(qreg[d+7],  k1.w, s1);
            s2 = fmaf(qreg[d+8],  k2.x, s2); s2 = fmaf(qreg[d+9],  k2.y, s2);
            s2 = fmaf(qreg[d+10], k2.z, s2); s2 = fmaf(qreg[d+11], k2.w, s2);
            s3 = fmaf(qreg[d+12], k3.x, s3); s3 = fmaf(qreg[d+13], k3.y, s3);
            s3 = fmaf(qreg[d+14], k3.z, s3); s3 = fmaf(qreg[d+15], k3.w, s3);
        }
        const float s = (s0 + s1) + (s2 + s3);
        sreg[wl] = (korigin + r >= 0) ? s : -INFINITY;
    }
    __syncthreads();   // all K reads done -> safe to overlay scores

    // exchange scores via smem (float4 stores/loads, conflict-free)
    {
        float* srow = &Ss[qi * ATT_PAD + hv * 32];
#pragma unroll
        for (int j = 0; j < 8; j++)
            *(float4*)&srow[4 * j] = make_float4(sreg[4*j], sreg[4*j+1], sreg[4*j+2], sreg[4*j+3]);
    }
    __syncthreads();

    // softmax over all 64 scores of this query
    float p[64];
    {
        const float* srow = &Ss[qi * ATT_PAD];
#pragma unroll
        for (int j = 0; j < 16; j++) {
            float4 t4 = *(const float4*)&srow[4 * j];
            p[4*j+0] = t4.x; p[4*j+1] = t4.y; p[4*j+2] = t4.z; p[4*j+3] = t4.w;
        }
    }
    float mx = -INFINITY;
#pragma unroll
    for (int w = 0; w < 64; w++) mx = fmaxf(mx, p[w]);
    float sum = 0.0f;
#pragma unroll
    for (int w = 0; w < 64; w++) { p[w] = __expf(p[w] - mx); sum += p[w]; }
    const float inv = 1.0f / sum;
#pragma unroll
    for (int w = 0; w < 64; w++) p[w] *= inv;

    // AV: own 32 head dims over all 64 window positions
    float accv[32];
#pragma unroll
    for (int d = 0; d < 32; d++) accv[d] = 0.0f;

    const int dbase = hv * 32;
#pragma unroll 4
    for (int w = 0; w < 64; w++) {
        const float pw = p[w];
        const float* vr = &Vs[(qi + w) * ATT_PAD + dbase];
#pragma unroll
        for (int d4 = 0; d4 < 8; d4++) {
            float4 vv = *(const float4*)&vr[4 * d4];
            accv[4*d4+0] = fmaf(pw, vv.x, accv[4*d4+0]);
            accv[4*d4+1] = fmaf(pw, vv.y, accv[4*d4+1]);
            accv[4*d4+2] = fmaf(pw, vv.z, accv[4*d4+2]);
            accv[4*d4+3] = fmaf(pw, vv.w, accv[4*d4+3]);
        }
    }

    // tf32-rounded output
    float* orow = &o[(size_t)(qstart + qi) * DM + hcol + dbase];
#pragma unroll
    for (int d4 = 0; d4 < 8; d4++)
        *(float4*)&orow[4 * d4] = make_float4(
            tf32_rna(accv[4*d4+0]), tf32_rna(accv[4*d4+1]),
            tf32_rna(accv[4*d4+2]), tf32_rna(accv[4*d4+3]));
}

// ---------------- launch ----------------
extern "C" void kernel_launch(void* const* d_in, const int* in_sizes, int n_in,
                              void* d_out, int out_size)
{
    const float* x  = (const float*)d_in[0];
    const float* Wq = (const float*)d_in[1];
    const float* Wk = (const float*)d_in[2];
    const float* Wv = (const float*)d_in[3];
    const float* Wo = (const float*)d_in[4];
    float* out = (float*)d_out;

    float *qp, *kp, *vp, *xr, *wr, *aor;
    cudaGetSymbolAddress((void**)&qp,  g_q);
    cudaGetSymbolAddress((void**)&kp,  g_k);
    cudaGetSymbolAddress((void**)&vp,  g_v);
    cudaGetSymbolAddress((void**)&xr,  g_xr);
    cudaGetSymbolAddress((void**)&wr,  g_wr);
    cudaGetSymbolAddress((void**)&aor, g_aor);

    cudaFuncSetAttribute(gemm_tf32, cudaFuncAttributeMaxDynamicSharedMemorySize, GEMM_SMEM);
    cudaFuncSetAttribute(swattn,    cudaFuncAttributeMaxDynamicSharedMemorySize, ATT_SMEM_BYTES);

    // 1. pre-round x and W to tf32
    round_x<<<(S_LEN * DM / 4 + 255) / 256, 256>>>(x, xr, S_LEN * DM / 4);
    round_w<<<dim3(DM * DM / 4 / 256, 4), 256>>>(Wq, Wk, Wv, Wo, wr);

    // 2. QKV projections (fused via grid.z)
    gemm_tf32<<<dim3(DM / 128, S_LEN / 128, 3), 128, GEMM_SMEM>>>(xr, wr, 0, qp, kp, vp);

    // 3. sliding-window attention
    swattn<<<dim3(S_LEN / 64, NH), 128, ATT_SMEM_BYTES>>>(qp, kp, vp, aor);

    // 4. output projection
    gemm_tf32<<<dim3(DM / 128, S_LEN / 128, 1), 128, GEMM_SMEM>>>(aor, wr, 3, out, out, out);
}

// round 6
// speedup vs baseline: 2.6142x; 1.1372x over previous
#include <cuda_runtime.h>
#include <cuda_bf16.h>
#include <cstdint>
#include <math.h>

#define S_LEN 4096
#define DM    1024
#define NH    16
#define HD    64
#define WIN   64

// ---------------- device scratch (no allocations allowed) ----------------
__device__ float g_q  [S_LEN * DM];
__device__ float g_k  [S_LEN * DM];
__device__ float g_v  [S_LEN * DM];
__device__ float g_xr [S_LEN * DM];      // tf32-rounded x
__device__ float g_wr [4 * DM * DM];     // tf32-rounded Wq,Wk,Wv,Wo
__device__ float g_aor[S_LEN * DM];      // tf32-rounded attention output

// ---------------- PTX helpers ----------------
__device__ __forceinline__ uint32_t smem_u32(const void* p) {
    uint32_t a;
    asm("{ .reg .u64 t; cvta.to.shared.u64 t, %1; cvt.u32.u64 %0, t; }" : "=r"(a) : "l"(p));
    return a;
}
#define CP16(dst, src) \
    asm volatile("cp.async.cg.shared.global [%0], [%1], 16;" :: "r"((uint32_t)(dst)), "l"(src) : "memory")
#define CP_COMMIT() asm volatile("cp.async.commit_group;" ::: "memory")
#define CP_WAIT1()  asm volatile("cp.async.wait_group 1;" ::: "memory")

#define LDSM4(r, addr) \
    asm volatile("ldmatrix.sync.aligned.m8n8.x4.shared.b16 {%0,%1,%2,%3}, [%4];" \
        : "=r"((r)[0]), "=r"((r)[1]), "=r"((r)[2]), "=r"((r)[3]) : "r"(addr))

#define MMA_TF32(d, a, b0v, b1v) \
    asm volatile("mma.sync.aligned.m16n8k8.row.col.f32.tf32.tf32.f32 " \
        "{%0,%1,%2,%3}, {%4,%5,%6,%7}, {%8,%9}, {%0,%1,%2,%3};" \
        : "+f"((d)[0]), "+f"((d)[1]), "+f"((d)[2]), "+f"((d)[3]) \
        : "r"((a)[0]), "r"((a)[1]), "r"((a)[2]), "r"((a)[3]), "r"(b0v), "r"(b1v))

__device__ __forceinline__ float tf32_rna(float x) {
    uint32_t t;
    asm("cvt.rna.tf32.f32 %0, %1;" : "=r"(t) : "f"(x));
    return __uint_as_float(t);
}

// ---------------- tf32 pre-round kernels ----------------
__global__ void round_x(const float* __restrict__ in, float* __restrict__ out, int n4) {
    int i = blockIdx.x * blockDim.x + threadIdx.x;
    if (i >= n4) return;
    float4 f = ((const float4*)in)[i];
    ((float4*)out)[i] = make_float4(tf32_rna(f.x), tf32_rna(f.y), tf32_rna(f.z), tf32_rna(f.w));
}

__global__ void round_w(const float* __restrict__ Wq, const float* __restrict__ Wk,
                        const float* __restrict__ Wv, const float* __restrict__ Wo,
                        float* __restrict__ out) {
    const float* W = blockIdx.y == 0 ? Wq : (blockIdx.y == 1 ? Wk : (blockIdx.y == 2 ? Wv : Wo));
    int i = blockIdx.x * blockDim.x + threadIdx.x;
    float4 f = ((const float4*)W)[i];
    ((float4*)(out + (size_t)blockIdx.y * DM * DM))[i] =
        make_float4(tf32_rna(f.x), tf32_rna(f.y), tf32_rna(f.z), tf32_rna(f.w));
}

// ---------------------------------------------------------------------------
// tf32 GEMM v3: C[M,N] = A[M,K] @ W[N,K]^T
// CTA 128x128, BK=32, 3-stage cp.async (prefetch depth 2), 4 warps (2x2),
// warp tile 64x64. __launch_bounds__(128,2): 2 CTAs/SM = 8 warps/SM.
// ---------------------------------------------------------------------------
#define TILE_B  16384                 // 128 rows x 128B (32 fp32)
#define STAGE_B (2 * TILE_B)
#define NSTAGE  3
#define GEMM_SMEM (NSTAGE * STAGE_B)  // 98304 -> 2 CTAs/SM

__global__ __launch_bounds__(128, 2) void gemm_tf32(
    const float* __restrict__ A, const float* __restrict__ Wr,
    int w_off, float* __restrict__ C0, float* __restrict__ C1, float* __restrict__ C2)
{
    extern __shared__ char sm[];
    const int z = blockIdx.z;
    const float* B = Wr + (size_t)(w_off + z) * DM * DM;
    float* C = z == 0 ? C0 : (z == 1 ? C1 : C2);

    const uint32_t smem_base = smem_u32(sm);
    const int tid  = threadIdx.x;
    const int lane = tid & 31;
    const int wid  = tid >> 5;
    const int wm   = wid & 1;    // M offset wm*64
    const int wn   = wid >> 1;   // N offset wn*64
    const int m0 = blockIdx.y * 128;
    const int n0 = blockIdx.x * 128;

    // cp.async mapping: 8 16B chunks per thread per tile (128 rows x 8 chunks)
    uint32_t swo[8], gA[8], gB[8];
#pragma unroll
    for (int jj = 0; jj < 8; jj++) {
        int q = tid + 128 * jj;
        int r = q >> 3, c = q & 7;
        swo[jj] = (uint32_t)(r * 128 + ((c ^ (r & 7)) << 4));
        gA[jj] = (uint32_t)((m0 + r) * DM + c * 4);
        gB[jj] = (uint32_t)((n0 + r) * DM + c * 4);
    }

    // ldmatrix addressing
    const int lm   = lane >> 3;
    const int lrow = lane & 7;
    const int cSel = lm >> 1;
    uint32_t aOff[4]; int aXor[4];
#pragma unroll
    for (int mi = 0; mi < 4; mi++) {
        int ar = wm * 64 + mi * 16 + (lm & 1) * 8 + lrow;
        aOff[mi] = (uint32_t)(ar * 128); aXor[mi] = ar & 7;
    }
    uint32_t bOff[4]; int bXor[4];
#pragma unroll
    for (int pb = 0; pb < 4; pb++) {
        int br = wn * 64 + pb * 16 + (lm & 1) * 8 + lrow;
        bOff[pb] = (uint32_t)(br * 128); bXor[pb] = br & 7;
    }

    float acc[4][8][4];
#pragma unroll
    for (int mi = 0; mi < 4; mi++)
#pragma unroll
        for (int nb = 0; nb < 8; nb++)
#pragma unroll
            for (int e = 0; e < 4; e++) acc[mi][nb][e] = 0.0f;

    const int ITERS = DM / 32;   // 32

    auto issue = [&](int t) {
        const uint32_t sb = smem_base + (uint32_t)(t % NSTAGE) * STAGE_B;
        const uint32_t kt = (uint32_t)(t * 32);
#pragma unroll
        for (int jj = 0; jj < 8; jj++) {
            CP16(sb + swo[jj],          (const char*)A + (size_t)(gA[jj] + kt) * 4);
            CP16(sb + TILE_B + swo[jj], (const char*)B + (size_t)(gB[jj] + kt) * 4);
        }
        CP_COMMIT();
    };

    issue(0); issue(1);

    for (int t = 0; t < ITERS; t++) {
        CP_WAIT1();          // stage t resident (<=1 group pending)
        __syncthreads();     // everyone done with slot (t+2)%3 from iter t-1
        if (t + 2 < ITERS) issue(t + 2);

        const uint32_t sb = smem_base + (uint32_t)(t % NSTAGE) * STAGE_B;
        const uint32_t aBase = sb, bBase = sb + TILE_B;

#pragma unroll
        for (int s = 0; s < 4; s++) {
            uint32_t fA[4][4];
#pragma unroll
            for (int mi = 0; mi < 4; mi++)
                LDSM4(fA[mi], aBase + aOff[mi] + (uint32_t)((((2 * s) + cSel) ^ aXor[mi]) << 4));
            uint32_t fB[8][2];
#pragma unroll
            for (int pb = 0; pb < 4; pb++) {
                uint32_t bt[4];
                LDSM4(bt, bBase + bOff[pb] + (uint32_t)((((2 * s) + cSel) ^ bXor[pb]) << 4));
                fB[2 * pb][0] = bt[0]; fB[2 * pb][1] = bt[2];
                fB[2 * pb + 1][0] = bt[1]; fB[2 * pb + 1][1] = bt[3];
            }
#pragma unroll
            for (int mi = 0; mi < 4; mi++)
#pragma unroll
                for (int nb = 0; nb < 8; nb++)
                    MMA_TF32(acc[mi][nb], fA[mi], fB[nb][0], fB[nb][1]);
        }
    }

    // epilogue
    const int crow0 = m0 + wm * 64 + (lane >> 2);
    const int ccol0 = n0 + wn * 64 + (lane & 3) * 2;
#pragma unroll
    for (int mi = 0; mi < 4; mi++) {
#pragma unroll
        for (int nb = 0; nb < 8; nb++) {
            const int row = crow0 + mi * 16;
            const int col = ccol0 + nb * 8;
            *(float2*)&C[(size_t)row * DM + col]       = make_float2(acc[mi][nb][0], acc[mi][nb][1]);
            *(float2*)&C[(size_t)(row + 8) * DM + col] = make_float2(acc[mi][nb][2], acc[mi][nb][3]);
        }
    }
}

// ---------------------------------------------------------------------------
// Sliding-window attention v3 (unchanged from R5 — 107.8us, conflict-free).
// ---------------------------------------------------------------------------
#define ATT_PAD 68
#define ATT_ROWS 127
#define ATT_SMEM_BYTES (2 * ATT_ROWS * ATT_PAD * 4)   // 69088

__global__ __launch_bounds__(128, 3) void swattn(
    const float* __restrict__ q, const float* __restrict__ k,
    const float* __restrict__ v, float* __restrict__ o)
{
    extern __shared__ float smf[];
    float* Ks = smf;
    float* Vs = smf + ATT_ROWS * ATT_PAD;
    float* Ss = smf;   // overlaid on K tile after QK phase

    const int qstart  = blockIdx.x * 64;
    const int h       = blockIdx.y;
    const int korigin = qstart - (WIN - 1);
    const int hcol    = h * HD;

    const int tid = threadIdx.x;
    const int qi  = tid & 63;
    const int hv  = tid >> 6;

    for (int i = tid; i < ATT_ROWS * 16; i += 128) {
        const int r  = i >> 4;
        const int c4 = (i & 15) << 2;
        const int g  = korigin + r;
        float4 kk = make_float4(0.f, 0.f, 0.f, 0.f);
        float4 vv = kk;
        if (g >= 0) {
            kk = *(const float4*)&k[(size_t)g * DM + hcol + c4];
            vv = *(const float4*)&v[(size_t)g * DM + hcol + c4];
        }
        *(float4*)&Ks[r * ATT_PAD + c4] = kk;
        *(float4*)&Vs[r * ATT_PAD + c4] = vv;
    }

    float qreg[64];
    {
        const float* qrow = &q[(size_t)(qstart + qi) * DM + hcol];
#pragma unroll
        for (int j = 0; j < 16; j++) {
            float4 t4 = *(const float4*)&qrow[4 * j];
            qreg[4*j+0] = t4.x * 0.125f;
            qreg[4*j+1] = t4.y * 0.125f;
            qreg[4*j+2] = t4.z * 0.125f;
            qreg[4*j+3] = t4.w * 0.125f;
        }
    }
    __syncthreads();

    float sreg[32];
#pragma unroll 2
    for (int wl = 0; wl < 32; wl++) {
        const int r = qi + hv * 32 + wl;
        const float* kr = &Ks[r * ATT_PAD];
        float s0 = 0.f, s1 = 0.f, s2 = 0.f, s3 = 0.f;
#pragma unroll
        for (int d = 0; d < 64; d += 16) {
            float4 k0 = *(const float4*)&kr[d];
            float4 k1 = *(const float4*)&kr[d + 4];
            float4 k2 = *(const float4*)&kr[d + 8];
            float4 k3 = *(const float4*)&kr[d + 12];
            s0 = fmaf(qreg[d+0],  k0.x, s0); s0 = fmaf(qreg[d+1],  k0.y, s0);
            s0 = fmaf(qreg[d+2],  k0.z, s0); s0 = fmaf(qreg[d+3],  k0.w, s0);
            s1 = fmaf(qreg[d+4],  k1.x, s1); s1 = fmaf(qreg[d+5],  k1.y, s1);
            s1 = fmaf(qreg[d+6],  k1.z, s1); s1 = fmaf(qreg[d+7],  k1.w, s1);
            s2 = fmaf(qreg[d+8],  k2.x, s2); s2 = fmaf(qreg[d+9],  k2.y, s2);
            s2 = fmaf(qreg[d+10], k2.z, s2); s2 = fmaf(qreg[d+11], k2.w, s2);
            s3 = fmaf(qreg[d+12], k3.x, s3); s3 = fmaf(qreg[d+13], k3.y, s3);
            s3 = fmaf(qreg[d+14], k3.z, s3); s3 = fmaf(qreg[d+15], k3.w, s3);
        }
        const float s = (s0 + s1) + (s2 + s3);
        sreg[wl] = (korigin + r >= 0) ? s : -INFINITY;
    }
    __syncthreads();

    {
        float* srow = &Ss[qi * ATT_PAD + hv * 32];
#pragma unroll
        for (int j = 0; j < 8; j++)
            *(float4*)&srow[4 * j] = make_float4(sreg[4*j], sreg[4*j+1], sreg[4*j+2], sreg[4*j+3]);
    }
    __syncthreads();

    float p[64];
    {
        const float* srow = &Ss[qi * ATT_PAD];
#pragma unroll
        for (int j = 0; j < 16; j++) {
            float4 t4 = *(const float4*)&srow[4 * j];
            p[4*j+0] = t4.x; p[4*j+1] = t4.y; p[4*j+2] = t4.z; p[4*j+3] = t4.w;
        }
    }
    float mx = -INFINITY;
#pragma unroll
    for (int w = 0; w < 64; w++) mx = fmaxf(mx, p[w]);
    float sum = 0.0f;
#pragma unroll
    for (int w = 0; w < 64; w++) { p[w] = __expf(p[w] - mx); sum += p[w]; }
    const float inv = 1.0f / sum;
#pragma unroll
    for (int w = 0; w < 64; w++) p[w] *= inv;

    float accv[32];
#pragma unroll
    for (int d = 0; d < 32; d++) accv[d] = 0.0f;

    const int dbase = hv * 32;
#pragma unroll 4
    for (int w = 0; w < 64; w++) {
        const float pw = p[w];
        const float* vr = &Vs[(qi + w) * ATT_PAD + dbase];
#pragma unroll
        for (int d4 = 0; d4 < 8; d4++) {
            float4 vv = *(const float4*)&vr[4 * d4];
            accv[4*d4+0] = fmaf(pw, vv.x, accv[4*d4+0]);
            accv[4*d4+1] = fmaf(pw, vv.y, accv[4*d4+1]);
            accv[4*d4+2] = fmaf(pw, vv.z, accv[4*d4+2]);
            accv[4*d4+3] = fmaf(pw, vv.w, accv[4*d4+3]);
        }
    }

    float* orow = &o[(size_t)(qstart + qi) * DM + hcol + dbase];
#pragma unroll
    for (int d4 = 0; d4 < 8; d4++)
        *(float4*)&orow[4 * d4] = make_float4(
            tf32_rna(accv[4*d4+0]), tf32_rna(accv[4*d4+1]),
            tf32_rna(accv[4*d4+2]), tf32_rna(accv[4*d4+3]));
}

// ---------------- launch ----------------
extern "C" void kernel_launch(void* const* d_in, const int* in_sizes, int n_in,
                              void* d_out, int out_size)
{
    const float* x  = (const float*)d_in[0];
    const float* Wq = (const float*)d_in[1];
    const float* Wk = (const float*)d_in[2];
    const float* Wv = (const float*)d_in[3];
    const float* Wo = (const float*)d_in[4];
    float* out = (float*)d_out;

    float *qp, *kp, *vp, *xr, *wr, *aor;
    cudaGetSymbolAddress((void**)&qp,  g_q);
    cudaGetSymbolAddress((void**)&kp,  g_k);
    cudaGetSymbolAddress((void**)&vp,  g_v);
    cudaGetSymbolAddress((void**)&xr,  g_xr);
    cudaGetSymbolAddress((void**)&wr,  g_wr);
    cudaGetSymbolAddress((void**)&aor, g_aor);

    cudaFuncSetAttribute(gemm_tf32, cudaFuncAttributeMaxDynamicSharedMemorySize, GEMM_SMEM);
    cudaFuncSetAttribute(swattn,    cudaFuncAttributeMaxDynamicSharedMemorySize, ATT_SMEM_BYTES);

    // 1. pre-round x and W to tf32
    round_x<<<(S_LEN * DM / 4 + 255) / 256, 256>>>(x, xr, S_LEN * DM / 4);
    round_w<<<dim3(DM * DM / 4 / 256, 4), 256>>>(Wq, Wk, Wv, Wo, wr);

    // 2. QKV projections (fused via grid.z)
    gemm_tf32<<<dim3(DM / 128, S_LEN / 128, 3), 128, GEMM_SMEM>>>(xr, wr, 0, qp, kp, vp);

    // 3. sliding-window attention
    swattn<<<dim3(S_LEN / 64, NH), 128, ATT_SMEM_BYTES>>>(qp, kp, vp, aor);

    // 4. output projection
    gemm_tf32<<<dim3(DM / 128, S_LEN / 128, 1), 128, GEMM_SMEM>>>(aor, wr, 3, out, out, out);
}

// round 7
// speedup vs baseline: 2.8964x; 1.1080x over previous
#include <cuda_runtime.h>
#include <cuda_bf16.h>
#include <cstdint>
#include <math.h>

#define S_LEN 4096
#define DM    1024
#define NH    16
#define HD    64
#define WIN   64

// ---------------- device scratch (no allocations allowed) ----------------
__device__ float g_q  [S_LEN * DM];
__device__ float g_k  [S_LEN * DM];
__device__ float g_v  [S_LEN * DM];
__device__ float g_xr [S_LEN * DM];      // tf32-rounded x
__device__ float g_wr [4 * DM * DM];     // tf32-rounded Wq,Wk,Wv,Wo
__device__ float g_aor[S_LEN * DM];      // tf32-rounded attention output

// ---------------- PTX helpers ----------------
__device__ __forceinline__ uint32_t smem_u32(const void* p) {
    uint32_t a;
    asm("{ .reg .u64 t; cvta.to.shared.u64 t, %1; cvt.u32.u64 %0, t; }" : "=r"(a) : "l"(p));
    return a;
}
#define CP16(dst, src) \
    asm volatile("cp.async.cg.shared.global [%0], [%1], 16;" :: "r"((uint32_t)(dst)), "l"(src) : "memory")
#define CP_COMMIT() asm volatile("cp.async.commit_group;" ::: "memory")
#define CP_WAIT1()  asm volatile("cp.async.wait_group 1;" ::: "memory")

#define LDSM4(r, addr) \
    asm volatile("ldmatrix.sync.aligned.m8n8.x4.shared.b16 {%0,%1,%2,%3}, [%4];" \
        : "=r"((r)[0]), "=r"((r)[1]), "=r"((r)[2]), "=r"((r)[3]) : "r"(addr))

#define MMA_TF32(d, a, b0v, b1v) \
    asm volatile("mma.sync.aligned.m16n8k8.row.col.f32.tf32.tf32.f32 " \
        "{%0,%1,%2,%3}, {%4,%5,%6,%7}, {%8,%9}, {%0,%1,%2,%3};" \
        : "+f"((d)[0]), "+f"((d)[1]), "+f"((d)[2]), "+f"((d)[3]) \
        : "r"((a)[0]), "r"((a)[1]), "r"((a)[2]), "r"((a)[3]), "r"(b0v), "r"(b1v))

__device__ __forceinline__ float tf32_rna(float x) {
    uint32_t t;
    asm("cvt.rna.tf32.f32 %0, %1;" : "=r"(t) : "f"(x));
    return __uint_as_float(t);
}

// ---------------- tf32 pre-round kernels ----------------
__global__ void round_x(const float* __restrict__ in, float* __restrict__ out, int n4) {
    int i = blockIdx.x * blockDim.x + threadIdx.x;
    if (i >= n4) return;
    float4 f = ((const float4*)in)[i];
    ((float4*)out)[i] = make_float4(tf32_rna(f.x), tf32_rna(f.y), tf32_rna(f.z), tf32_rna(f.w));
}

__global__ void round_w(const float* __restrict__ Wq, const float* __restrict__ Wk,
                        const float* __restrict__ Wv, const float* __restrict__ Wo,
                        float* __restrict__ out) {
    const float* W = blockIdx.y == 0 ? Wq : (blockIdx.y == 1 ? Wk : (blockIdx.y == 2 ? Wv : Wo));
    int i = blockIdx.x * blockDim.x + threadIdx.x;
    float4 f = ((const float4*)W)[i];
    ((float4*)(out + (size_t)blockIdx.y * DM * DM))[i] =
        make_float4(tf32_rna(f.x), tf32_rna(f.y), tf32_rna(f.z), tf32_rna(f.w));
}

// ---------------------------------------------------------------------------
// tf32 GEMM v3 (unchanged from R6): CTA 128x128, BK=32, 3-stage, 2 CTAs/SM.
// ---------------------------------------------------------------------------
#define TILE_B  16384
#define STAGE_B (2 * TILE_B)
#define NSTAGE  3
#define GEMM_SMEM (NSTAGE * STAGE_B)  // 98304

__global__ __launch_bounds__(128, 2) void gemm_tf32(
    const float* __restrict__ A, const float* __restrict__ Wr,
    int w_off, float* __restrict__ C0, float* __restrict__ C1, float* __restrict__ C2)
{
    extern __shared__ char sm[];
    const int z = blockIdx.z;
    const float* B = Wr + (size_t)(w_off + z) * DM * DM;
    float* C = z == 0 ? C0 : (z == 1 ? C1 : C2);

    const uint32_t smem_base = smem_u32(sm);
    const int tid  = threadIdx.x;
    const int lane = tid & 31;
    const int wid  = tid >> 5;
    const int wm   = wid & 1;
    const int wn   = wid >> 1;
    const int m0 = blockIdx.y * 128;
    const int n0 = blockIdx.x * 128;

    uint32_t swo[8], gA[8], gB[8];
#pragma unroll
    for (int jj = 0; jj < 8; jj++) {
        int q = tid + 128 * jj;
        int r = q >> 3, c = q & 7;
        swo[jj] = (uint32_t)(r * 128 + ((c ^ (r & 7)) << 4));
        gA[jj] = (uint32_t)((m0 + r) * DM + c * 4);
        gB[jj] = (uint32_t)((n0 + r) * DM + c * 4);
    }

    const int lm   = lane >> 3;
    const int lrow = lane & 7;
    const int cSel = lm >> 1;
    uint32_t aOff[4]; int aXor[4];
#pragma unroll
    for (int mi = 0; mi < 4; mi++) {
        int ar = wm * 64 + mi * 16 + (lm & 1) * 8 + lrow;
        aOff[mi] = (uint32_t)(ar * 128); aXor[mi] = ar & 7;
    }
    uint32_t bOff[4]; int bXor[4];
#pragma unroll
    for (int pb = 0; pb < 4; pb++) {
        int br = wn * 64 + pb * 16 + (lm & 1) * 8 + lrow;
        bOff[pb] = (uint32_t)(br * 128); bXor[pb] = br & 7;
    }

    float acc[4][8][4];
#pragma unroll
    for (int mi = 0; mi < 4; mi++)
#pragma unroll
        for (int nb = 0; nb < 8; nb++)
#pragma unroll
            for (int e = 0; e < 4; e++) acc[mi][nb][e] = 0.0f;

    const int ITERS = DM / 32;

    auto issue = [&](int t) {
        const uint32_t sb = smem_base + (uint32_t)(t % NSTAGE) * STAGE_B;
        const uint32_t kt = (uint32_t)(t * 32);
#pragma unroll
        for (int jj = 0; jj < 8; jj++) {
            CP16(sb + swo[jj],          (const char*)A + (size_t)(gA[jj] + kt) * 4);
            CP16(sb + TILE_B + swo[jj], (const char*)B + (size_t)(gB[jj] + kt) * 4);
        }
        CP_COMMIT();
    };

    issue(0); issue(1);

    for (int t = 0; t < ITERS; t++) {
        CP_WAIT1();
        __syncthreads();
        if (t + 2 < ITERS) issue(t + 2);

        const uint32_t sb = smem_base + (uint32_t)(t % NSTAGE) * STAGE_B;
        const uint32_t aBase = sb, bBase = sb + TILE_B;

#pragma unroll
        for (int s = 0; s < 4; s++) {
            uint32_t fA[4][4];
#pragma unroll
            for (int mi = 0; mi < 4; mi++)
                LDSM4(fA[mi], aBase + aOff[mi] + (uint32_t)((((2 * s) + cSel) ^ aXor[mi]) << 4));
            uint32_t fB[8][2];
#pragma unroll
            for (int pb = 0; pb < 4; pb++) {
                uint32_t bt[4];
                LDSM4(bt, bBase + bOff[pb] + (uint32_t)((((2 * s) + cSel) ^ bXor[pb]) << 4));
                fB[2 * pb][0] = bt[0]; fB[2 * pb][1] = bt[2];
                fB[2 * pb + 1][0] = bt[1]; fB[2 * pb + 1][1] = bt[3];
            }
#pragma unroll
            for (int mi = 0; mi < 4; mi++)
#pragma unroll
                for (int nb = 0; nb < 8; nb++)
                    MMA_TF32(acc[mi][nb], fA[mi], fB[nb][0], fB[nb][1]);
        }
    }

    const int crow0 = m0 + wm * 64 + (lane >> 2);
    const int ccol0 = n0 + wn * 64 + (lane & 3) * 2;
#pragma unroll
    for (int mi = 0; mi < 4; mi++) {
#pragma unroll
        for (int nb = 0; nb < 8; nb++) {
            const int row = crow0 + mi * 16;
            const int col = ccol0 + nb * 8;
            *(float2*)&C[(size_t)row * DM + col]       = make_float2(acc[mi][nb][0], acc[mi][nb][1]);
            *(float2*)&C[(size_t)(row + 8) * DM + col] = make_float2(acc[mi][nb][2], acc[mi][nb][3]);
        }
    }
}

// ---------------------------------------------------------------------------
// Sliding-window attention v4: shared K/V row reads serve both queries of a
// pair.  Block = 64 queries, 128 threads.  Lane group of 4: qg=tid>>2 owns
// queries {2qg, 2qg+1}; hv=tid&3 owns a d-quarter via the chunk table
//   c(hv,j) = (hv&1) + ((hv>>1)<<2) + ((j&1)<<1) + ((j>>1)<<3)
// chosen so every 8-lane LDS.128 phase hits 8 distinct 16B banks.
// Row loop i=0..64: one K row read -> dots for both queries -> 4-lane shfl
// combine; thread keeps its own query's scores (e = hv&1).  p exchanged via
// smem overlay on the dead K tile (stride 67).  AV re-walks rows, one V row
// read feeds both queries' accumulators.  smem 69KB -> 3 CTAs/SM.
// ---------------------------------------------------------------------------
#define ATT_PAD 68
#define ATT_ROWS 127
#define PS_STR 67
#define ATT_SMEM_BYTES (2 * ATT_ROWS * ATT_PAD * 4)   // 69088

__global__ __launch_bounds__(128, 3) void swattn(
    const float* __restrict__ q, const float* __restrict__ k,
    const float* __restrict__ v, float* __restrict__ o)
{
    extern __shared__ float smf[];
    float* Ks = smf;
    float* Vs = smf + ATT_ROWS * ATT_PAD;
    float* Ps = smf;   // overlay on K tile after QK phase (64 x 67 floats)

    const int qstart  = blockIdx.x * 64;
    const int h       = blockIdx.y;
    const int korigin = qstart - (WIN - 1);
    const int hcol    = h * HD;

    const int tid = threadIdx.x;
    const int qg  = tid >> 2;       // 0..31: query pair {2qg, 2qg+1}
    const int hv  = tid & 3;        // d-quarter
    const int e   = hv & 1;         // which query this thread's scores belong to

    // chunk indices for this thread's d-quarter (16B chunks of the 64-float row)
    int ch[4];
#pragma unroll
    for (int j = 0; j < 4; j++)
        ch[j] = (hv & 1) + ((hv >> 1) << 2) + ((j & 1) << 1) + ((j >> 1) << 3);

    // ---- load K,V tiles (127 rows x 64 cols), zero-filled below range ----
    for (int i = tid; i < ATT_ROWS * 16; i += 128) {
        const int r  = i >> 4;
        const int c4 = (i & 15) << 2;
        const int g  = korigin + r;
        float4 kk = make_float4(0.f, 0.f, 0.f, 0.f);
        float4 vv = kk;
        if (g >= 0) {
            kk = *(const float4*)&k[(size_t)g * DM + hcol + c4];
            vv = *(const float4*)&v[(size_t)g * DM + hcol + c4];
        }
        *(float4*)&Ks[r * ATT_PAD + c4] = kk;
        *(float4*)&Vs[r * ATT_PAD + c4] = vv;
    }

    // ---- q chunks for BOTH queries of the pair, pre-scaled ----
    float qreg[2][16];
#pragma unroll
    for (int eq = 0; eq < 2; eq++) {
        const float* qrow = &q[(size_t)(qstart + 2 * qg + eq) * DM + hcol];
#pragma unroll
        for (int j = 0; j < 4; j++) {
            float4 t4 = *(const float4*)&qrow[4 * ch[j]];
            qreg[eq][4*j+0] = t4.x * 0.125f;
            qreg[eq][4*j+1] = t4.y * 0.125f;
            qreg[eq][4*j+2] = t4.z * 0.125f;
            qreg[eq][4*j+3] = t4.w * 0.125f;
        }
    }
    __syncthreads();

    // ---- QK: one shared K row per i serves both queries ----
    float s[65];
#pragma unroll
    for (int i = 0; i <= 64; i++) {
        const int r = 2 * qg + i;
        const float* kr = &Ks[r * ATT_PAD];
        float u0 = 0.f, u1 = 0.f, w0 = 0.f, w1 = 0.f;
#pragma unroll
        for (int j = 0; j < 4; j++) {
            float4 kk = *(const float4*)&kr[4 * ch[j]];
            if (j & 1) {
                u1 = fmaf(qreg[0][4*j+0], kk.x, u1); u1 = fmaf(qreg[0][4*j+1], kk.y, u1);
                u1 = fmaf(qreg[0][4*j+2], kk.z, u1); u1 = fmaf(qreg[0][4*j+3], kk.w, u1);
                w1 = fmaf(qreg[1][4*j+0], kk.x, w1); w1 = fmaf(qreg[1][4*j+1], kk.y, w1);
                w1 = fmaf(qreg[1][4*j+2], kk.z, w1); w1 = fmaf(qreg[1][4*j+3], kk.w, w1);
            } else {
                u0 = fmaf(qreg[0][4*j+0], kk.x, u0); u0 = fmaf(qreg[0][4*j+1], kk.y, u0);
                u0 = fmaf(qreg[0][4*j+2], kk.z, u0); u0 = fmaf(qreg[0][4*j+3], kk.w, u0);
                w0 = fmaf(qreg[1][4*j+0], kk.x, w0); w0 = fmaf(qreg[1][4*j+1], kk.y, w0);
                w0 = fmaf(qreg[1][4*j+2], kk.z, w0); w0 = fmaf(qreg[1][4*j+3], kk.w, w0);
            }
        }
        float u = u0 + u1;       // partial dot: q0 . K[r] (this d-quarter)
        float wv = w0 + w1;      // partial dot: q1 . K[r]
        u  += __shfl_xor_sync(0xffffffffu, u, 1);
        u  += __shfl_xor_sync(0xffffffffu, u, 2);
        wv += __shfl_xor_sync(0xffffffffu, wv, 1);
        wv += __shfl_xor_sync(0xffffffffu, wv, 2);
        const float sc = e ? wv : u;
        // validity: key in range, and window index w = i - e in [0, 63]
        const bool valid = (korigin + r >= 0) && (e ? (i >= 1) : (i <= 63));
        s[i] = valid ? sc : -INFINITY;
    }

    // ---- softmax over this thread's query (65 slots, invalid = -inf) ----
    float mx = -INFINITY;
#pragma unroll
    for (int i = 0; i <= 64; i++) mx = fmaxf(mx, s[i]);
    float sum = 0.0f;
#pragma unroll
    for (int i = 0; i <= 64; i++) { s[i] = __expf(s[i] - mx); sum += s[i]; }
    const float inv = 1.0f / sum;
#pragma unroll
    for (int i = 0; i <= 64; i++) s[i] *= inv;

    __syncthreads();   // all K reads done -> safe to overlay Ps

    // ---- store p (only hv<2 lanes: one writer per query) ----
    if (hv < 2) {
        const int base = (2 * qg + e) * PS_STR;
#pragma unroll
        for (int i = 0; i <= 64; i++) {
            const int w = i - e;
            if (w >= 0 && w <= 63) Ps[base + w] = s[i];
        }
    }
    __syncthreads();

    // ---- AV: one shared V row per i feeds both queries ----
    float accv[2][16];
#pragma unroll
    for (int d = 0; d < 16; d++) { accv[0][d] = 0.f; accv[1][d] = 0.f; }

#pragma unroll 4
    for (int i = 0; i <= 64; i++) {
        const int r = 2 * qg + i;
        const float pw0 = (i <= 63) ? Ps[(2 * qg) * PS_STR + i]         : 0.f;
        const float pw1 = (i >= 1)  ? Ps[(2 * qg + 1) * PS_STR + i - 1] : 0.f;
        const float* vr = &Vs[r * ATT_PAD];
#pragma unroll
        for (int j = 0; j < 4; j++) {
            float4 vv = *(const float4*)&vr[4 * ch[j]];
            accv[0][4*j+0] = fmaf(pw0, vv.x, accv[0][4*j+0]);
            accv[0][4*j+1] = fmaf(pw0, vv.y, accv[0][4*j+1]);
            accv[0][4*j+2] = fmaf(pw0, vv.z, accv[0][4*j+2]);
            accv[0][4*j+3] = fmaf(pw0, vv.w, accv[0][4*j+3]);
            accv[1][4*j+0] = fmaf(pw1, vv.x, accv[1][4*j+0]);
            accv[1][4*j+1] = fmaf(pw1, vv.y, accv[1][4*j+1]);
            accv[1][4*j+2] = fmaf(pw1, vv.z, accv[1][4*j+2]);
            accv[1][4*j+3] = fmaf(pw1, vv.w, accv[1][4*j+3]);
        }
    }

    // ---- write tf32-rounded output for both queries (own d-quarter) ----
#pragma unroll
    for (int eq = 0; eq < 2; eq++) {
        float* orow = &o[(size_t)(qstart + 2 * qg + eq) * DM + hcol];
#pragma unroll
        for (int j = 0; j < 4; j++)
            *(float4*)&orow[4 * ch[j]] = make_float4(
                tf32_rna(accv[eq][4*j+0]), tf32_rna(accv[eq][4*j+1]),
                tf32_rna(accv[eq][4*j+2]), tf32_rna(accv[eq][4*j+3]));
    }
}

// ---------------- launch ----------------
extern "C" void kernel_launch(void* const* d_in, const int* in_sizes, int n_in,
                              void* d_out, int out_size)
{
    const float* x  = (const float*)d_in[0];
    const float* Wq = (const float*)d_in[1];
    const float* Wk = (const float*)d_in[2];
    const float* Wv = (const float*)d_in[3];
    const float* Wo = (const float*)d_in[4];
    float* out = (float*)d_out;

    float *qp, *kp, *vp, *xr, *wr, *aor;
    cudaGetSymbolAddress((void**)&qp,  g_q);
    cudaGetSymbolAddress((void**)&kp,  g_k);
    cudaGetSymbolAddress((void**)&vp,  g_v);
    cudaGetSymbolAddress((void**)&xr,  g_xr);
    cudaGetSymbolAddress((void**)&wr,  g_wr);
    cudaGetSymbolAddress((void**)&aor, g_aor);

    cudaFuncSetAttribute(gemm_tf32, cudaFuncAttributeMaxDynamicSharedMemorySize, GEMM_SMEM);
    cudaFuncSetAttribute(swattn,    cudaFuncAttributeMaxDynamicSharedMemorySize, ATT_SMEM_BYTES);

    // 1. pre-round x and W to tf32
    round_x<<<(S_LEN * DM / 4 + 255) / 256, 256>>>(x, xr, S_LEN * DM / 4);
    round_w<<<dim3(DM * DM / 4 / 256, 4), 256>>>(Wq, Wk, Wv, Wo, wr);

    // 2. QKV projections (fused via grid.z)
    gemm_tf32<<<dim3(DM / 128, S_LEN / 128, 3), 128, GEMM_SMEM>>>(xr, wr, 0, qp, kp, vp);

    // 3. sliding-window attention
    swattn<<<dim3(S_LEN / 64, NH), 128, ATT_SMEM_BYTES>>>(qp, kp, vp, aor);

    // 4. output projection
    gemm_tf32<<<dim3(DM / 128, S_LEN / 128, 1), 128, GEMM_SMEM>>>(aor, wr, 3, out, out, out);
}